// round 2
// baseline (speedup 1.0000x reference)
#include <cuda_runtime.h>
#include <math.h>

#define NTOK  65536
#define DH    256
#define DF    1024
#define NB    4
#define TM    64
#define FB    128
#define XS_STRIDE 260   // padded: row-delta of 4 rows -> 16 banks apart (no broadcast-pair conflict)
#define HS_STRIDE 132

__device__ int g_counts[NB];
__device__ int g_idx[NB * NTOK];

__global__ void reset_counts_kernel() {
    if (threadIdx.x < NB) g_counts[threadIdx.x] = 0;
}

__global__ void bucket_kernel(const int* __restrict__ b_seq) {
    int i = blockIdx.x * blockDim.x + threadIdx.x;
    int b = b_seq[i];
    if (b > 0) {
        int pos = atomicAdd(&g_counts[b - 1], 1);
        g_idx[(b - 1) * NTOK + pos] = i;
    }
}

// one float4 of the output per thread; zero rows whose branch selector is 0
__global__ void zero_kernel(const int* __restrict__ b_seq, float4* __restrict__ out) {
    int gid = blockIdx.x * blockDim.x + threadIdx.x;   // NTOK*64 threads
    int tok = gid >> 6;
    if (b_seq[tok] == 0) out[gid] = make_float4(0.f, 0.f, 0.f, 0.f);
}

__global__ __launch_bounds__(256, 1)
void ffn_kernel(const float* __restrict__ x,
                const float* __restrict__ w1, const float* __restrict__ b1,
                const float* __restrict__ w2, const float* __restrict__ b2,
                const float* __restrict__ gamma, const float* __restrict__ beta,
                float* __restrict__ out)
{
    const int br = blockIdx.y;
    const int count = g_counts[br];
    const int t0 = blockIdx.x * TM;
    if (t0 >= count) return;

    extern __shared__ float smem[];
    float* Xs = smem;                         // TM * XS_STRIDE (reused as LN output buffer)
    float* Hs = Xs + TM * XS_STRIDE;          // TM * HS_STRIDE
    float* Ws = Hs + TM * HS_STRIDE;          // 4096 floats, shared by W1-slab and W2-slab
    int* s_tok = (int*)(Ws + 4096);           // TM

    const int tid = threadIdx.x;
    const int tx = tid & 15;
    const int ty = tid >> 4;

    if (tid < TM) {
        int r = t0 + tid;
        s_tok[tid] = g_idx[br * NTOK + (r < count ? r : count - 1)];
    }
    __syncthreads();

    // gather x tile: 4 threads per row, 16 float4 each
    {
        int row = tid >> 2, q = tid & 3;
        const float4* src = (const float4*)(x + (size_t)s_tok[row] * DH) + q * 16;
        float4* dst = (float4*)(Xs + row * XS_STRIDE) + q * 16;
        #pragma unroll
        for (int v = 0; v < 16; v++) dst[v] = src[v];
    }

    const float* w1b = w1 + (size_t)br * DF * DH;
    const float* w2b = w2 + (size_t)br * DH * DF;

    float acc2[4][16];
    #pragma unroll
    for (int i = 0; i < 4; i++)
        #pragma unroll
        for (int j = 0; j < 16; j++) acc2[i][j] = 0.f;

    __syncthreads();

    for (int f0 = 0; f0 < DF; f0 += FB) {
        float c1[4][8];
        #pragma unroll
        for (int i = 0; i < 4; i++)
            #pragma unroll
            for (int j = 0; j < 8; j++) c1[i][j] = 0.f;

        // ---- GEMM1: c1[64x128] = X[64x256] * W1[f0:f0+128, :]^T ----
        for (int k0 = 0; k0 < DH; k0 += 32) {
            // stage W1 slab transposed: Ws[kk][f], kk in [0,32), f in [0,128)
            {
                int fr = tid >> 1, half = tid & 1;
                const float4* src = (const float4*)(w1b + (size_t)(f0 + fr) * DH + k0 + half * 16);
                #pragma unroll
                for (int v = 0; v < 4; v++) {
                    float4 d = src[v];
                    int kk = half * 16 + v * 4;
                    Ws[(kk + 0) * FB + fr] = d.x;
                    Ws[(kk + 1) * FB + fr] = d.y;
                    Ws[(kk + 2) * FB + fr] = d.z;
                    Ws[(kk + 3) * FB + fr] = d.w;
                }
            }
            __syncthreads();
            #pragma unroll 8
            for (int kk = 0; kk < 32; kk++) {
                float4 bA = *(const float4*)(Ws + kk * FB + tx * 4);
                float4 bB = *(const float4*)(Ws + kk * FB + 64 + tx * 4);
                #pragma unroll
                for (int i = 0; i < 4; i++) {
                    float a = Xs[(ty * 4 + i) * XS_STRIDE + k0 + kk];
                    c1[i][0] += a * bA.x; c1[i][1] += a * bA.y;
                    c1[i][2] += a * bA.z; c1[i][3] += a * bA.w;
                    c1[i][4] += a * bB.x; c1[i][5] += a * bB.y;
                    c1[i][6] += a * bB.z; c1[i][7] += a * bB.w;
                }
            }
            __syncthreads();
        }

        // ---- bias + ELU -> Hs ----
        {
            float b1v[8];
            #pragma unroll
            for (int j = 0; j < 8; j++) {
                int fl = (j >> 2) * 64 + tx * 4 + (j & 3);
                b1v[j] = b1[br * DF + f0 + fl];
            }
            #pragma unroll
            for (int i = 0; i < 4; i++) {
                int m = ty * 4 + i;
                #pragma unroll
                for (int g = 0; g < 2; g++) {
                    float4 hv;
                    float v0 = c1[i][g*4+0] + b1v[g*4+0]; hv.x = v0 > 0.f ? v0 : expf(v0) - 1.f;
                    float v1 = c1[i][g*4+1] + b1v[g*4+1]; hv.y = v1 > 0.f ? v1 : expf(v1) - 1.f;
                    float v2 = c1[i][g*4+2] + b1v[g*4+2]; hv.z = v2 > 0.f ? v2 : expf(v2) - 1.f;
                    float v3 = c1[i][g*4+3] + b1v[g*4+3]; hv.w = v3 > 0.f ? v3 : expf(v3) - 1.f;
                    *(float4*)(Hs + m * HS_STRIDE + g * 64 + tx * 4) = hv;
                }
            }
        }
        __syncthreads();

        // ---- GEMM2: acc2[64x256] += Hs[64x128] * W2[:, f0:f0+128]^T ----
        for (int fs0 = 0; fs0 < FB; fs0 += 16) {
            // stage W2 slab transposed: Ws[ff][h], ff in [0,16), h in [0,256)
            {
                const float4* src = (const float4*)(w2b + (size_t)tid * DF + f0 + fs0);
                #pragma unroll
                for (int v = 0; v < 4; v++) {
                    float4 d = src[v];
                    Ws[(v * 4 + 0) * DH + tid] = d.x;
                    Ws[(v * 4 + 1) * DH + tid] = d.y;
                    Ws[(v * 4 + 2) * DH + tid] = d.z;
                    Ws[(v * 4 + 3) * DH + tid] = d.w;
                }
            }
            __syncthreads();
            #pragma unroll 4
            for (int ff = 0; ff < 16; ff++) {
                float4 bg0 = *(const float4*)(Ws + ff * DH +   0 + tx * 4);
                float4 bg1 = *(const float4*)(Ws + ff * DH +  64 + tx * 4);
                float4 bg2 = *(const float4*)(Ws + ff * DH + 128 + tx * 4);
                float4 bg3 = *(const float4*)(Ws + ff * DH + 192 + tx * 4);
                #pragma unroll
                for (int i = 0; i < 4; i++) {
                    float a = Hs[(ty * 4 + i) * HS_STRIDE + fs0 + ff];
                    acc2[i][0]  += a * bg0.x; acc2[i][1]  += a * bg0.y;
                    acc2[i][2]  += a * bg0.z; acc2[i][3]  += a * bg0.w;
                    acc2[i][4]  += a * bg1.x; acc2[i][5]  += a * bg1.y;
                    acc2[i][6]  += a * bg1.z; acc2[i][7]  += a * bg1.w;
                    acc2[i][8]  += a * bg2.x; acc2[i][9]  += a * bg2.y;
                    acc2[i][10] += a * bg2.z; acc2[i][11] += a * bg2.w;
                    acc2[i][12] += a * bg3.x; acc2[i][13] += a * bg3.y;
                    acc2[i][14] += a * bg3.z; acc2[i][15] += a * bg3.w;
                }
            }
            __syncthreads();
        }
    }

    // ---- bias b2, two-pass LayerNorm (16-lane shuffles), stage into Xs ----
    {
        float b2v[16], gv[16], bev[16];
        #pragma unroll
        for (int j = 0; j < 16; j++) {
            int h = (j >> 2) * 64 + tx * 4 + (j & 3);
            b2v[j] = b2[br * DH + h];
            gv[j]  = gamma[br * DH + h];
            bev[j] = beta[br * DH + h];
        }
        #pragma unroll
        for (int i = 0; i < 4; i++) {
            float sum = 0.f;
            #pragma unroll
            for (int j = 0; j < 16; j++) { acc2[i][j] += b2v[j]; sum += acc2[i][j]; }
            #pragma unroll
            for (int o = 1; o < 16; o <<= 1) sum += __shfl_xor_sync(0xffffffffu, sum, o, 16);
            float mu = sum * (1.f / 256.f);
            float sq = 0.f;
            #pragma unroll
            for (int j = 0; j < 16; j++) { float d = acc2[i][j] - mu; sq += d * d; }
            #pragma unroll
            for (int o = 1; o < 16; o <<= 1) sq += __shfl_xor_sync(0xffffffffu, sq, o, 16);
            float rstd = rsqrtf(sq * (1.f / 256.f) + 1e-12f);
            int m = ty * 4 + i;
            #pragma unroll
            for (int g = 0; g < 4; g++) {
                float4 ov;
                ov.x = (acc2[i][g*4+0] - mu) * rstd * gv[g*4+0] + bev[g*4+0];
                ov.y = (acc2[i][g*4+1] - mu) * rstd * gv[g*4+1] + bev[g*4+1];
                ov.z = (acc2[i][g*4+2] - mu) * rstd * gv[g*4+2] + bev[g*4+2];
                ov.w = (acc2[i][g*4+3] - mu) * rstd * gv[g*4+3] + bev[g*4+3];
                *(float4*)(Xs + m * XS_STRIDE + g * 64 + tx * 4) = ov;
            }
        }
    }
    __syncthreads();

    // ---- scatter to output ----
    {
        int row = tid >> 2, q = tid & 3;
        int r = t0 + row;
        if (r < count) {
            float4* dst = (float4*)(out + (size_t)s_tok[row] * DH) + q * 16;
            const float4* src = (const float4*)(Xs + row * XS_STRIDE) + q * 16;
            #pragma unroll
            for (int v = 0; v < 16; v++) dst[v] = src[v];
        }
    }
}

extern "C" void kernel_launch(void* const* d_in, const int* in_sizes, int n_in,
                              void* d_out, int out_size) {
    const float* x     = (const float*)d_in[0];
    const int*   b_seq = (const int*)d_in[1];
    const float* w1    = (const float*)d_in[2];
    const float* b1    = (const float*)d_in[3];
    const float* w2    = (const float*)d_in[4];
    const float* b2    = (const float*)d_in[5];
    const float* gamma = (const float*)d_in[6];
    const float* beta  = (const float*)d_in[7];
    float* out = (float*)d_out;

    const int smem_bytes = (TM * XS_STRIDE + TM * HS_STRIDE + 4096) * 4 + TM * 4;
    cudaFuncSetAttribute(ffn_kernel, cudaFuncAttributeMaxDynamicSharedMemorySize, smem_bytes);

    reset_counts_kernel<<<1, 32>>>();
    bucket_kernel<<<NTOK / 256, 256>>>(b_seq);
    zero_kernel<<<(NTOK * 64) / 256, 256>>>(b_seq, (float4*)out);
    ffn_kernel<<<dim3(NTOK / TM, NB), 256, smem_bytes>>>(x, w1, b1, w2, b2, gamma, beta, out);
}

// round 4
// speedup vs baseline: 1.9570x; 1.9570x over previous
#include <cuda_runtime.h>
#include <math.h>
#include <stdint.h>

#define NTOK 65536
#define DH 256
#define DF 1024
#define NB 4
#define TM 64
#define THREADS 256

#define XS_STRIDE 260
#define HS_STRIDE 132
#define SB_STRIDE 36

// smem offsets in u32 units
#define OFF_TOK 0
#define OFF_RED 64
#define OFF_XS 320
#define OFF_HS (OFF_XS + 64 * XS_STRIDE)
#define OFF_SB1 (OFF_HS + 64 * HS_STRIDE)
#define OFF_SB2 (OFF_SB1 + 2 * 128 * SB_STRIDE)
#define SMEM_U32 (OFF_SB2 + 2 * 256 * SB_STRIDE)

__device__ int g_counts[NB];
__device__ int g_idx[NB * NTOK];

__global__ void reset_counts_kernel() {
    if (threadIdx.x < NB) g_counts[threadIdx.x] = 0;
}

__global__ void bucket_kernel(const int* __restrict__ b_seq) {
    int i = blockIdx.x * blockDim.x + threadIdx.x;
    int b = b_seq[i];
    if (b > 0) {
        int pos = atomicAdd(&g_counts[b - 1], 1);
        g_idx[(b - 1) * NTOK + pos] = i;
    }
}

__global__ void zero_kernel(const int* __restrict__ b_seq, float4* __restrict__ out) {
    int gid = blockIdx.x * blockDim.x + threadIdx.x;   // NTOK*64 threads
    int tok = gid >> 6;
    if (b_seq[tok] == 0) out[gid] = make_float4(0.f, 0.f, 0.f, 0.f);
}

static __device__ __forceinline__ uint32_t f2tf(float f) {
    uint32_t r; asm("cvt.rna.tf32.f32 %0, %1;" : "=r"(r) : "f"(f)); return r;
}

static __device__ __forceinline__ void mma8(float* c,
    uint32_t a0, uint32_t a1, uint32_t a2, uint32_t a3, uint32_t b0, uint32_t b1) {
    asm volatile("mma.sync.aligned.m16n8k8.row.col.f32.tf32.tf32.f32 "
                 "{%0,%1,%2,%3}, {%4,%5,%6,%7}, {%8,%9}, {%0,%1,%2,%3};"
                 : "+f"(c[0]), "+f"(c[1]), "+f"(c[2]), "+f"(c[3])
                 : "r"(a0), "r"(a1), "r"(a2), "r"(a3), "r"(b0), "r"(b1));
}

// permuted column within a 16-k group: c = (k&3)*4 + ((k>>2)&3), groups kept in place
static __device__ __forceinline__ int permc(int col) {
    return (col & ~15) + ((col & 3) * 4) + ((col >> 2) & 3);
}

__global__ __launch_bounds__(THREADS, 1)
void ffn_mma_kernel(const float* __restrict__ x,
                    const float* __restrict__ w1, const float* __restrict__ b1,
                    const float* __restrict__ w2, const float* __restrict__ b2,
                    const float* __restrict__ gamma, const float* __restrict__ beta,
                    float* __restrict__ out)
{
    const int br = blockIdx.y;
    const int count = g_counts[br];
    const int t0 = blockIdx.x * TM;
    if (t0 >= count) return;

    extern __shared__ uint32_t smem[];
    int* s_tok = (int*)(smem + OFF_TOK);
    float* red = (float*)(smem + OFF_RED);
    uint32_t* Xs = smem + OFF_XS;
    uint32_t* Hs = smem + OFF_HS;
    uint32_t* SB1 = smem + OFF_SB1;
    uint32_t* SB2 = smem + OFF_SB2;

    const int tid = threadIdx.x;
    const int wid = tid >> 5, lane = tid & 31;
    const int g = lane >> 2, tig = lane & 3;
    const int wm = wid & 1, wn = wid >> 1;   // GEMM1: 32x32 warp tile; GEMM2: 32x64

    if (tid < TM) {
        int r = t0 + tid;
        s_tok[tid] = g_idx[br * NTOK + (r < count ? r : count - 1)];
    }
    __syncthreads();

    // ---- stage X tile (once), tf32 + k-permuted ----
    {
        int row = tid >> 2, q = tid & 3;
        const float4* src = (const float4*)(x + (size_t)s_tok[row] * DH) + q * 16;
        uint32_t* xr = Xs + row * XS_STRIDE + q * 64;
        #pragma unroll
        for (int j = 0; j < 16; j++) {
            float4 d = src[j];
            int grp = (j >> 2) * 16, jj = j & 3;
            xr[grp + jj]      = f2tf(d.x);
            xr[grp + 4 + jj]  = f2tf(d.y);
            xr[grp + 8 + jj]  = f2tf(d.z);
            xr[grp + 12 + jj] = f2tf(d.w);
        }
    }

    const float* w1b = w1 + (size_t)br * DF * DH;
    const float* w2b = w2 + (size_t)br * DH * DF;
    const int f1 = tid >> 1, half1 = tid & 1;

    float acc2[2][8][4];
    #pragma unroll
    for (int a = 0; a < 2; a++)
        #pragma unroll
        for (int bq = 0; bq < 8; bq++)
            #pragma unroll
            for (int cq = 0; cq < 4; cq++) acc2[a][bq][cq] = 0.f;

    for (int fc = 0; fc < 8; fc++) {
        // ================= GEMM1: C1[64x128] = X[64x256] * W1chunk^T =================
        float c1[2][4][4];
        #pragma unroll
        for (int a = 0; a < 2; a++)
            #pragma unroll
            for (int bq = 0; bq < 4; bq++)
                #pragma unroll
                for (int cq = 0; cq < 4; cq++) c1[a][bq][cq] = 0.f;

        float4 wr[4];
        {
            const float4* p = (const float4*)(w1b + (size_t)(fc * 128 + f1) * DH + half1 * 16);
            #pragma unroll
            for (int j = 0; j < 4; j++) wr[j] = p[j];
        }
        for (int s = 0; s < 8; s++) {
            __syncthreads();
            {   // STS current slab (tf32, permuted): slab[f][16*half + perm]
                uint32_t* d = SB1 + (s & 1) * (128 * SB_STRIDE) + f1 * SB_STRIDE + half1 * 16;
                #pragma unroll
                for (int j = 0; j < 4; j++) {
                    d[j]      = f2tf(wr[j].x);
                    d[4 + j]  = f2tf(wr[j].y);
                    d[8 + j]  = f2tf(wr[j].z);
                    d[12 + j] = f2tf(wr[j].w);
                }
            }
            __syncthreads();
            if (s < 7) {
                const float4* p = (const float4*)(w1b + (size_t)(fc * 128 + f1) * DH + (s + 1) * 32 + half1 * 16);
                #pragma unroll
                for (int j = 0; j < 4; j++) wr[j] = p[j];
            }
            const uint32_t* bbuf = SB1 + (s & 1) * (128 * SB_STRIDE);
            #pragma unroll
            for (int k16 = 0; k16 < 2; k16++) {
                int cb = s * 32 + k16 * 16 + 4 * tig;
                int scb = k16 * 16 + 4 * tig;
                uint4 aL[2], aH[2], bf[4];
                #pragma unroll
                for (int mt = 0; mt < 2; mt++) {
                    int r0 = wm * 32 + mt * 16 + g;
                    aL[mt] = *(const uint4*)(Xs + r0 * XS_STRIDE + cb);
                    aH[mt] = *(const uint4*)(Xs + (r0 + 8) * XS_STRIDE + cb);
                }
                #pragma unroll
                for (int nt = 0; nt < 4; nt++) {
                    int n = wn * 32 + nt * 8 + g;
                    bf[nt] = *(const uint4*)(bbuf + n * SB_STRIDE + scb);
                }
                #pragma unroll
                for (int mt = 0; mt < 2; mt++)
                    #pragma unroll
                    for (int nt = 0; nt < 4; nt++) {
                        mma8(c1[mt][nt], aL[mt].x, aH[mt].x, aL[mt].y, aH[mt].y, bf[nt].x, bf[nt].y);
                        mma8(c1[mt][nt], aL[mt].z, aH[mt].z, aL[mt].w, aH[mt].w, bf[nt].z, bf[nt].w);
                    }
            }
        }

        // ================= bias + ELU -> Hs (tf32, permuted) =================
        {
            const float* b1g = b1 + br * DF + fc * 128;
            #pragma unroll
            for (int nt = 0; nt < 4; nt++) {
                int col0 = wn * 32 + nt * 8 + 2 * tig;
                float ba = b1g[col0], bb = b1g[col0 + 1];
                int pc0 = permc(col0), pc1 = permc(col0 + 1);
                #pragma unroll
                for (int mt = 0; mt < 2; mt++) {
                    int r0 = wm * 32 + mt * 16 + g;
                    float v00 = c1[mt][nt][0] + ba;
                    float v01 = c1[mt][nt][1] + bb;
                    float v10 = c1[mt][nt][2] + ba;
                    float v11 = c1[mt][nt][3] + bb;
                    v00 = v00 > 0.f ? v00 : expm1f(v00);
                    v01 = v01 > 0.f ? v01 : expm1f(v01);
                    v10 = v10 > 0.f ? v10 : expm1f(v10);
                    v11 = v11 > 0.f ? v11 : expm1f(v11);
                    Hs[r0 * HS_STRIDE + pc0] = f2tf(v00);
                    Hs[r0 * HS_STRIDE + pc1] = f2tf(v01);
                    Hs[(r0 + 8) * HS_STRIDE + pc0] = f2tf(v10);
                    Hs[(r0 + 8) * HS_STRIDE + pc1] = f2tf(v11);
                }
            }
        }

        // ================= GEMM2: acc2[64x256] += H[64x128] * W2chunk^T =================
        float4 w2r[8];
        {
            const float4* p = (const float4*)(w2b + (size_t)tid * DF + fc * 128);
            #pragma unroll
            for (int j = 0; j < 8; j++) w2r[j] = p[j];
        }
        for (int s = 0; s < 4; s++) {
            __syncthreads();
            {
                uint32_t* d = SB2 + (s & 1) * (256 * SB_STRIDE) + tid * SB_STRIDE;
                #pragma unroll
                for (int j = 0; j < 8; j++) {
                    int grp = (j >> 2) * 16, jj = j & 3;
                    d[grp + jj]      = f2tf(w2r[j].x);
                    d[grp + 4 + jj]  = f2tf(w2r[j].y);
                    d[grp + 8 + jj]  = f2tf(w2r[j].z);
                    d[grp + 12 + jj] = f2tf(w2r[j].w);
                }
            }
            __syncthreads();
            if (s < 3) {
                const float4* p = (const float4*)(w2b + (size_t)tid * DF + fc * 128 + (s + 1) * 32);
                #pragma unroll
                for (int j = 0; j < 8; j++) w2r[j] = p[j];
            }
            const uint32_t* bbuf = SB2 + (s & 1) * (256 * SB_STRIDE);
            #pragma unroll
            for (int k16 = 0; k16 < 2; k16++) {
                int cb = s * 32 + k16 * 16 + 4 * tig;
                int scb = k16 * 16 + 4 * tig;
                uint4 aL[2], aH[2];
                #pragma unroll
                for (int mt = 0; mt < 2; mt++) {
                    int r0 = wm * 32 + mt * 16 + g;
                    aL[mt] = *(const uint4*)(Hs + r0 * HS_STRIDE + cb);
                    aH[mt] = *(const uint4*)(Hs + (r0 + 8) * HS_STRIDE + cb);
                }
                #pragma unroll
                for (int nt = 0; nt < 8; nt++) {
                    int n = wn * 64 + nt * 8 + g;
                    uint4 bf = *(const uint4*)(bbuf + n * SB_STRIDE + scb);
                    #pragma unroll
                    for (int mt = 0; mt < 2; mt++) {
                        mma8(acc2[mt][nt], aL[mt].x, aH[mt].x, aL[mt].y, aH[mt].y, bf.x, bf.y);
                        mma8(acc2[mt][nt], aL[mt].z, aH[mt].z, aL[mt].w, aH[mt].w, bf.z, bf.w);
                    }
                }
            }
        }
    }

    // ================= epilogue: b2 + exact LayerNorm + scatter =================
    {
        const float* b2g = b2 + br * DH;
        #pragma unroll
        for (int nt = 0; nt < 8; nt++) {
            int col0 = wn * 64 + nt * 8 + 2 * tig;
            float2 bb = *(const float2*)(b2g + col0);
            #pragma unroll
            for (int mt = 0; mt < 2; mt++) {
                acc2[mt][nt][0] += bb.x; acc2[mt][nt][1] += bb.y;
                acc2[mt][nt][2] += bb.x; acc2[mt][nt][3] += bb.y;
            }
        }
        __syncthreads();
        float mu[4], rstd[4];
        #pragma unroll
        for (int rr = 0; rr < 4; rr++) {
            int mt = rr >> 1, hi = rr & 1;
            float sfull = 0.f;
            #pragma unroll
            for (int nt = 0; nt < 8; nt++) sfull += acc2[mt][nt][hi * 2] + acc2[mt][nt][hi * 2 + 1];
            sfull += __shfl_xor_sync(0xffffffffu, sfull, 1);
            sfull += __shfl_xor_sync(0xffffffffu, sfull, 2);
            int row = wm * 32 + mt * 16 + hi * 8 + g;
            if (tig == 0) red[row * 4 + wn] = sfull;
        }
        __syncthreads();
        #pragma unroll
        for (int rr = 0; rr < 4; rr++) {
            int mt = rr >> 1, hi = rr & 1;
            int row = wm * 32 + mt * 16 + hi * 8 + g;
            mu[rr] = (red[row * 4] + red[row * 4 + 1] + red[row * 4 + 2] + red[row * 4 + 3]) * (1.f / 256.f);
        }
        __syncthreads();
        #pragma unroll
        for (int rr = 0; rr < 4; rr++) {
            int mt = rr >> 1, hi = rr & 1;
            float sq = 0.f;
            #pragma unroll
            for (int nt = 0; nt < 8; nt++) {
                float d0 = acc2[mt][nt][hi * 2] - mu[rr];
                float d1 = acc2[mt][nt][hi * 2 + 1] - mu[rr];
                sq += d0 * d0 + d1 * d1;
            }
            sq += __shfl_xor_sync(0xffffffffu, sq, 1);
            sq += __shfl_xor_sync(0xffffffffu, sq, 2);
            int row = wm * 32 + mt * 16 + hi * 8 + g;
            if (tig == 0) red[row * 4 + wn] = sq;
        }
        __syncthreads();
        #pragma unroll
        for (int rr = 0; rr < 4; rr++) {
            int mt = rr >> 1, hi = rr & 1;
            int row = wm * 32 + mt * 16 + hi * 8 + g;
            float var = (red[row * 4] + red[row * 4 + 1] + red[row * 4 + 2] + red[row * 4 + 3]) * (1.f / 256.f);
            rstd[rr] = rsqrtf(var + 1e-12f);
        }

        const float* gg = gamma + br * DH;
        const float* be = beta + br * DH;
        #pragma unroll
        for (int rr = 0; rr < 4; rr++) {
            int mt = rr >> 1, hi = rr & 1;
            int row = wm * 32 + mt * 16 + hi * 8 + g;
            if (t0 + row < count) {
                float* o = out + (size_t)s_tok[row] * DH;
                #pragma unroll
                for (int nt = 0; nt < 8; nt++) {
                    int col0 = wn * 64 + nt * 8 + 2 * tig;
                    float2 gm = *(const float2*)(gg + col0);
                    float2 bt = *(const float2*)(be + col0);
                    float2 v;
                    v.x = (acc2[mt][nt][hi * 2] - mu[rr]) * rstd[rr] * gm.x + bt.x;
                    v.y = (acc2[mt][nt][hi * 2 + 1] - mu[rr]) * rstd[rr] * gm.y + bt.y;
                    *(float2*)(o + col0) = v;
                }
            }
        }
    }
}

extern "C" void kernel_launch(void* const* d_in, const int* in_sizes, int n_in,
                              void* d_out, int out_size) {
    const float* x     = (const float*)d_in[0];
    const int*   b_seq = (const int*)d_in[1];
    const float* w1    = (const float*)d_in[2];
    const float* b1    = (const float*)d_in[3];
    const float* w2    = (const float*)d_in[4];
    const float* b2    = (const float*)d_in[5];
    const float* gamma = (const float*)d_in[6];
    const float* beta  = (const float*)d_in[7];
    float* out = (float*)d_out;

    const int smem_bytes = SMEM_U32 * 4;
    cudaFuncSetAttribute(ffn_mma_kernel, cudaFuncAttributeMaxDynamicSharedMemorySize, smem_bytes);

    reset_counts_kernel<<<1, 32>>>();
    bucket_kernel<<<NTOK / 256, 256>>>(b_seq);
    zero_kernel<<<(NTOK * 64) / 256, 256>>>(b_seq, (float4*)out);
    ffn_mma_kernel<<<dim3(NTOK / TM, NB), THREADS, smem_bytes>>>(x, w1, b1, w2, b2, gamma, beta, out);
}

// round 7
// speedup vs baseline: 2.1415x; 1.0942x over previous
#include <cuda_runtime.h>
#include <math.h>
#include <stdint.h>

#define NTOK 65536
#define DH 256
#define DF 1024
#define NB 4
#define TM 64
#define THREADS 256

#define XS_STRIDE 264
#define HS_STRIDE 136
#define SB_STRIDE 40
#define SB1_BUF (128 * SB_STRIDE)
#define SB2_BUF (256 * SB_STRIDE)

// smem offsets in u32 units
#define OFF_TOK 0
#define OFF_RED 64
#define OFF_XS 320
#define OFF_HS (OFF_XS + 64 * XS_STRIDE)
#define OFF_SB (OFF_HS + 64 * HS_STRIDE)
#define SMEM_U32 (OFF_SB + 4 * SB1_BUF)   // 4*5120 == 2*10240

__device__ int g_counts[NB];
__device__ int g_idx[NB * NTOK];
__device__ uint32_t g_w1p[NB * DF * DH];   // [br][fc8][s8][f128][perm32]
__device__ uint32_t g_w2p[NB * DH * DF];   // [br][fc8][s4][h256][perm32]

static __device__ __forceinline__ uint32_t f2tf(float f) {
    uint32_t r; asm("cvt.rna.tf32.f32 %0, %1;" : "=r"(r) : "f"(f)); return r;
}
static __device__ __forceinline__ uint32_t smem_u32(const void* p) {
    uint32_t a;
    asm("{ .reg .u64 t; cvta.to.shared.u64 t, %1; cvt.u32.u64 %0, t; }" : "=r"(a) : "l"(p));
    return a;
}
#define CP16(dst, src) asm volatile("cp.async.cg.shared.global [%0], [%1], 16;" :: "r"(dst), "l"(src) : "memory")
#define CP_COMMIT() asm volatile("cp.async.commit_group;" ::: "memory")
#define CP_WAIT(n) asm volatile("cp.async.wait_group %0;" :: "n"(n) : "memory")

static __device__ __forceinline__ void mma8(float* c,
    uint32_t a0, uint32_t a1, uint32_t a2, uint32_t a3, uint32_t b0, uint32_t b1) {
    asm volatile("mma.sync.aligned.m16n8k8.row.col.f32.tf32.tf32.f32 "
                 "{%0,%1,%2,%3}, {%4,%5,%6,%7}, {%8,%9}, {%0,%1,%2,%3};"
                 : "+f"(c[0]), "+f"(c[1]), "+f"(c[2]), "+f"(c[3])
                 : "r"(a0), "r"(a1), "r"(a2), "r"(a3), "r"(b0), "r"(b1));
}
static __device__ __forceinline__ int permc(int col) {
    return (col & ~15) + ((col & 3) * 4) + ((col >> 2) & 3);
}

__global__ void reset_counts_kernel() {
    if (threadIdx.x < NB) g_counts[threadIdx.x] = 0;
}
__global__ void bucket_kernel(const int* __restrict__ b_seq) {
    int i = blockIdx.x * blockDim.x + threadIdx.x;
    int b = b_seq[i];
    if (b > 0) {
        int pos = atomicAdd(&g_counts[b - 1], 1);
        g_idx[(b - 1) * NTOK + pos] = i;
    }
}
__global__ void zero_kernel(const int* __restrict__ b_seq, float4* __restrict__ out) {
    int gid = blockIdx.x * blockDim.x + threadIdx.x;
    int tok = gid >> 6;
    if (b_seq[tok] == 0) out[gid] = make_float4(0.f, 0.f, 0.f, 0.f);
}

// w1 [NB][DF][DH] -> tf32 permuted slabs
__global__ void prep_w1_kernel(const float* __restrict__ w1) {
    int t = blockIdx.x * blockDim.x + threadIdx.x;
    int e = t * 4;
    int br = e >> 18;
    int rem = e & 262143;
    int f = rem >> 8;
    int k = rem & 255;
    float4 v = *(const float4*)(w1 + e);
    int fc = f >> 7, fl = f & 127, s = k >> 5, c = k & 31;
    uint32_t* dst = g_w1p + ((((br * 8 + fc) * 8 + s) * 128 + fl) << 5) + (c & 16) + ((c & 15) >> 2);
    dst[0] = f2tf(v.x); dst[4] = f2tf(v.y); dst[8] = f2tf(v.z); dst[12] = f2tf(v.w);
}
// w2 [NB][DH][DF] -> tf32 permuted slabs
__global__ void prep_w2_kernel(const float* __restrict__ w2) {
    int t = blockIdx.x * blockDim.x + threadIdx.x;
    int e = t * 4;
    int br = e >> 18;
    int rem = e & 262143;
    int h = rem >> 10;
    int f = rem & 1023;
    float4 v = *(const float4*)(w2 + e);
    int fc = f >> 7, s = (f >> 5) & 3, c = f & 31;
    uint32_t* dst = g_w2p + ((((br * 8 + fc) * 4 + s) * 256 + h) << 5) + (c & 16) + ((c & 15) >> 2);
    dst[0] = f2tf(v.x); dst[4] = f2tf(v.y); dst[8] = f2tf(v.z); dst[12] = f2tf(v.w);
}

__global__ __launch_bounds__(THREADS, 1)
void ffn_mma_kernel(const float* __restrict__ x,
                    const float* __restrict__ b1, const float* __restrict__ b2,
                    const float* __restrict__ gamma, const float* __restrict__ beta,
                    float* __restrict__ out)
{
    const int br = blockIdx.y;
    const int count = g_counts[br];
    const int t0 = blockIdx.x * TM;
    if (t0 >= count) return;

    extern __shared__ uint32_t smem[];
    int* s_tok = (int*)(smem + OFF_TOK);
    float* red = (float*)(smem + OFF_RED);
    uint32_t* Xs = smem + OFF_XS;
    uint32_t* Hs = smem + OFF_HS;
    uint32_t* SB = smem + OFF_SB;
    const uint32_t sb_byte = smem_u32(smem) + OFF_SB * 4;

    const int tid = threadIdx.x;
    const int wid = tid >> 5, lane = tid & 31;
    const int g = lane >> 2, tig = lane & 3;
    const int wm = wid & 1, wn = wid >> 1;

    if (tid < TM) {
        int r = t0 + tid;
        s_tok[tid] = g_idx[br * NTOK + (r < count ? r : count - 1)];
    }
    __syncthreads();

    // ---- stage X tile (once), tf32 + k-permuted ----
    {
        int row = tid >> 2, q = tid & 3;
        const float4* src = (const float4*)(x + (size_t)s_tok[row] * DH) + q * 16;
        uint32_t* xr = Xs + row * XS_STRIDE + q * 64;
        #pragma unroll
        for (int j = 0; j < 16; j++) {
            float4 d = src[j];
            int grp = (j >> 2) * 16, jj = j & 3;
            xr[grp + jj]      = f2tf(d.x);
            xr[grp + 4 + jj]  = f2tf(d.y);
            xr[grp + 8 + jj]  = f2tf(d.z);
            xr[grp + 12 + jj] = f2tf(d.w);
        }
    }

    // staging coords
    const int f1 = tid >> 1, half1 = tid & 1;
    const uint32_t st1_dst = sb_byte + (f1 * SB_STRIDE + half1 * 16) * 4;
    const uint32_t st2_dst = sb_byte + tid * SB_STRIDE * 4;
    const uint32_t* w1base = g_w1p + (size_t)br * 8 * 8 * 4096;
    const uint32_t* w2base = g_w2p + (size_t)br * 8 * 4 * 8192;

    float acc2[2][8][4];
    #pragma unroll
    for (int a = 0; a < 2; a++)
        #pragma unroll
        for (int bq = 0; bq < 8; bq++)
            #pragma unroll
            for (int cq = 0; cq < 4; cq++) acc2[a][bq][cq] = 0.f;

    for (int fc = 0; fc < 8; fc++) {
        // ================= GEMM1: C1[64x128] = X * W1chunk^T =================
        float c1[2][4][4];
        #pragma unroll
        for (int a = 0; a < 2; a++)
            #pragma unroll
            for (int bq = 0; bq < 4; bq++)
                #pragma unroll
                for (int cq = 0; cq < 4; cq++) c1[a][bq][cq] = 0.f;

        const uint32_t* w1s = w1base + fc * 8 * 4096 + f1 * 32 + half1 * 16;
        __syncthreads();   // SB free from previous phase
        {
            const uint32_t* s0 = w1s;
            CP16(st1_dst, s0); CP16(st1_dst + 16, s0 + 4);
            CP16(st1_dst + 32, s0 + 8); CP16(st1_dst + 48, s0 + 12);
            CP_COMMIT();
            const uint32_t* s1 = w1s + 4096;
            uint32_t d1 = st1_dst + SB1_BUF * 4;
            CP16(d1, s1); CP16(d1 + 16, s1 + 4);
            CP16(d1 + 32, s1 + 8); CP16(d1 + 48, s1 + 12);
            CP_COMMIT();
        }
        for (int s = 0; s < 8; s++) {
            if (s + 2 < 8) {
                const uint32_t* sp = w1s + (s + 2) * 4096;
                uint32_t dp = st1_dst + ((s + 2) & 3) * SB1_BUF * 4;
                CP16(dp, sp); CP16(dp + 16, sp + 4);
                CP16(dp + 32, sp + 8); CP16(dp + 48, sp + 12);
                CP_COMMIT();
            }
            if (s < 6) { CP_WAIT(2); } else if (s == 6) { CP_WAIT(1); } else { CP_WAIT(0); }
            __syncthreads();
            const uint32_t* bbuf = SB + (s & 3) * SB1_BUF;
            #pragma unroll
            for (int k16 = 0; k16 < 2; k16++) {
                int cb = s * 32 + k16 * 16 + 4 * tig;
                int scb = k16 * 16 + 4 * tig;
                uint4 aL[2], aH[2], bf[4];
                #pragma unroll
                for (int mt = 0; mt < 2; mt++) {
                    int r0 = wm * 32 + mt * 16 + g;
                    aL[mt] = *(const uint4*)(Xs + r0 * XS_STRIDE + cb);
                    aH[mt] = *(const uint4*)(Xs + (r0 + 8) * XS_STRIDE + cb);
                }
                #pragma unroll
                for (int nt = 0; nt < 4; nt++) {
                    int n = wn * 32 + nt * 8 + g;
                    bf[nt] = *(const uint4*)(bbuf + n * SB_STRIDE + scb);
                }
                #pragma unroll
                for (int mt = 0; mt < 2; mt++)
                    #pragma unroll
                    for (int nt = 0; nt < 4; nt++) {
                        mma8(c1[mt][nt], aL[mt].x, aH[mt].x, aL[mt].y, aH[mt].y, bf[nt].x, bf[nt].y);
                        mma8(c1[mt][nt], aL[mt].z, aH[mt].z, aL[mt].w, aH[mt].w, bf[nt].z, bf[nt].w);
                    }
            }
        }

        // ================= bias + ELU -> Hs =================
        {
            const float* b1g = b1 + br * DF + fc * 128;
            #pragma unroll
            for (int nt = 0; nt < 4; nt++) {
                int col0 = wn * 32 + nt * 8 + 2 * tig;
                float ba = b1g[col0], bb = b1g[col0 + 1];
                int pc0 = permc(col0), pc1 = permc(col0 + 1);
                #pragma unroll
                for (int mt = 0; mt < 2; mt++) {
                    int r0 = wm * 32 + mt * 16 + g;
                    float v00 = c1[mt][nt][0] + ba;
                    float v01 = c1[mt][nt][1] + bb;
                    float v10 = c1[mt][nt][2] + ba;
                    float v11 = c1[mt][nt][3] + bb;
                    v00 = v00 > 0.f ? v00 : expm1f(v00);
                    v01 = v01 > 0.f ? v01 : expm1f(v01);
                    v10 = v10 > 0.f ? v10 : expm1f(v10);
                    v11 = v11 > 0.f ? v11 : expm1f(v11);
                    Hs[r0 * HS_STRIDE + pc0] = f2tf(v00);
                    Hs[r0 * HS_STRIDE + pc1] = f2tf(v01);
                    Hs[(r0 + 8) * HS_STRIDE + pc0] = f2tf(v10);
                    Hs[(r0 + 8) * HS_STRIDE + pc1] = f2tf(v11);
                }
            }
        }
        __syncthreads();   // Hs complete; SB free for GEMM2 staging

        // ================= GEMM2: acc2[64x256] += H * W2chunk^T =================
        const uint32_t* w2s = w2base + fc * 4 * 8192 + tid * 32;
        {
            const uint32_t* s0 = w2s;
            #pragma unroll
            for (int j = 0; j < 8; j++) CP16(st2_dst + j * 16, s0 + j * 4);
            CP_COMMIT();
        }
        for (int s = 0; s < 4; s++) {
            if (s + 1 < 4) {
                const uint32_t* sp = w2s + (s + 1) * 8192;
                uint32_t dp = st2_dst + ((s + 1) & 1) * SB2_BUF * 4;
                #pragma unroll
                for (int j = 0; j < 8; j++) CP16(dp + j * 16, sp + j * 4);
                CP_COMMIT();
            }
            if (s < 3) { CP_WAIT(1); } else { CP_WAIT(0); }
            __syncthreads();
            const uint32_t* bbuf = SB + (s & 1) * SB2_BUF;
            #pragma unroll
            for (int k16 = 0; k16 < 2; k16++) {
                int cb = s * 32 + k16 * 16 + 4 * tig;
                int scb = k16 * 16 + 4 * tig;
                uint4 aL[2], aH[2];
                #pragma unroll
                for (int mt = 0; mt < 2; mt++) {
                    int r0 = wm * 32 + mt * 16 + g;
                    aL[mt] = *(const uint4*)(Hs + r0 * HS_STRIDE + cb);
                    aH[mt] = *(const uint4*)(Hs + (r0 + 8) * HS_STRIDE + cb);
                }
                #pragma unroll
                for (int nt = 0; nt < 8; nt++) {
                    int n = wn * 64 + nt * 8 + g;
                    uint4 bf = *(const uint4*)(bbuf + n * SB_STRIDE + scb);
                    #pragma unroll
                    for (int mt = 0; mt < 2; mt++) {
                        mma8(acc2[mt][nt], aL[mt].x, aH[mt].x, aL[mt].y, aH[mt].y, bf.x, bf.y);
                        mma8(acc2[mt][nt], aL[mt].z, aH[mt].z, aL[mt].w, aH[mt].w, bf.z, bf.w);
                    }
                }
            }
            if (s < 3) __syncthreads();
        }
    }

    // ================= epilogue: b2 + exact LayerNorm + scatter =================
    {
        const float* b2g = b2 + br * DH;
        #pragma unroll
        for (int nt = 0; nt < 8; nt++) {
            int col0 = wn * 64 + nt * 8 + 2 * tig;
            float2 bb = *(const float2*)(b2g + col0);
            #pragma unroll
            for (int mt = 0; mt < 2; mt++) {
                acc2[mt][nt][0] += bb.x; acc2[mt][nt][1] += bb.y;
                acc2[mt][nt][2] += bb.x; acc2[mt][nt][3] += bb.y;
            }
        }
        __syncthreads();
        float mu[4], rstd[4];
        #pragma unroll
        for (int rr = 0; rr < 4; rr++) {
            int mt = rr >> 1, hi = rr & 1;
            float sfull = 0.f;
            #pragma unroll
            for (int nt = 0; nt < 8; nt++) sfull += acc2[mt][nt][hi * 2] + acc2[mt][nt][hi * 2 + 1];
            sfull += __shfl_xor_sync(0xffffffffu, sfull, 1);
            sfull += __shfl_xor_sync(0xffffffffu, sfull, 2);
            int row = wm * 32 + mt * 16 + hi * 8 + g;
            if (tig == 0) red[row * 4 + wn] = sfull;
        }
        __syncthreads();
        #pragma unroll
        for (int rr = 0; rr < 4; rr++) {
            int mt = rr >> 1, hi = rr & 1;
            int row = wm * 32 + mt * 16 + hi * 8 + g;
            mu[rr] = (red[row * 4] + red[row * 4 + 1] + red[row * 4 + 2] + red[row * 4 + 3]) * (1.f / 256.f);
        }
        __syncthreads();
        #pragma unroll
        for (int rr = 0; rr < 4; rr++) {
            int mt = rr >> 1, hi = rr & 1;
            float sq = 0.f;
            #pragma unroll
            for (int nt = 0; nt < 8; nt++) {
                float d0 = acc2[mt][nt][hi * 2] - mu[rr];
                float d1 = acc2[mt][nt][hi * 2 + 1] - mu[rr];
                sq += d0 * d0 + d1 * d1;
            }
            sq += __shfl_xor_sync(0xffffffffu, sq, 1);
            sq += __shfl_xor_sync(0xffffffffu, sq, 2);
            int row = wm * 32 + mt * 16 + hi * 8 + g;
            if (tig == 0) red[row * 4 + wn] = sq;
        }
        __syncthreads();
        #pragma unroll
        for (int rr = 0; rr < 4; rr++) {
            int mt = rr >> 1, hi = rr & 1;
            int row = wm * 32 + mt * 16 + hi * 8 + g;
            float var = (red[row * 4] + red[row * 4 + 1] + red[row * 4 + 2] + red[row * 4 + 3]) * (1.f / 256.f);
            rstd[rr] = rsqrtf(var + 1e-12f);
        }

        const float* gg = gamma + br * DH;
        const float* be = beta + br * DH;
        #pragma unroll
        for (int rr = 0; rr < 4; rr++) {
            int mt = rr >> 1, hi = rr & 1;
            int row = wm * 32 + mt * 16 + hi * 8 + g;
            if (t0 + row < count) {
                float* o = out + (size_t)s_tok[row] * DH;
                #pragma unroll
                for (int nt = 0; nt < 8; nt++) {
                    int col0 = wn * 64 + nt * 8 + 2 * tig;
                    float2 gm = *(const float2*)(gg + col0);
                    float2 bt = *(const float2*)(be + col0);
                    float2 v;
                    v.x = (acc2[mt][nt][hi * 2] - mu[rr]) * rstd[rr] * gm.x + bt.x;
                    v.y = (acc2[mt][nt][hi * 2 + 1] - mu[rr]) * rstd[rr] * gm.y + bt.y;
                    *(float2*)(o + col0) = v;
                }
            }
        }
    }
}

extern "C" void kernel_launch(void* const* d_in, const int* in_sizes, int n_in,
                              void* d_out, int out_size) {
    const float* x     = (const float*)d_in[0];
    const int*   b_seq = (const int*)d_in[1];
    const float* w1    = (const float*)d_in[2];
    const float* b1    = (const float*)d_in[3];
    const float* w2    = (const float*)d_in[4];
    const float* b2    = (const float*)d_in[5];
    const float* gamma = (const float*)d_in[6];
    const float* beta  = (const float*)d_in[7];
    float* out = (float*)d_out;

    const int smem_bytes = SMEM_U32 * 4;
    cudaFuncSetAttribute(ffn_mma_kernel, cudaFuncAttributeMaxDynamicSharedMemorySize, smem_bytes);

    reset_counts_kernel<<<1, 32>>>();
    bucket_kernel<<<NTOK / 256, 256>>>(b_seq);
    prep_w1_kernel<<<NB * DF * DH / 4 / 256, 256>>>(w1);
    prep_w2_kernel<<<NB * DH * DF / 4 / 256, 256>>>(w2);
    zero_kernel<<<(NTOK * 64) / 256, 256>>>(b_seq, (float4*)out);
    ffn_mma_kernel<<<dim3(NTOK / TM, NB), THREADS, smem_bytes>>>(x, b1, b2, gamma, beta, out);
}

// round 8
// speedup vs baseline: 3.7192x; 1.7367x over previous
#include <cuda_runtime.h>
#include <math.h>
#include <stdint.h>

#define NTOK 65536
#define DH 256
#define DF 1024
#define NB 4
#define TM 64
#define THREADS 256

#define XS_STRIDE 272   // ≡16 (mod 32): conflict-free uint4 LDS phases
#define HS_STRIDE 144

// smem offsets in u32 units
#define OFF_TOK 0
#define OFF_RED 64
#define OFF_XS 320
#define OFF_HS (OFF_XS + 64 * XS_STRIDE)
#define SMEM_U32 (OFF_HS + 64 * HS_STRIDE)

__device__ int g_counts[NB];
__device__ int g_idx[NB * NTOK];
__device__ uint4 g_w1p[NB * DF * DH / 4];   // [br][fc8][s8][f128][perm32] as uint4
__device__ uint4 g_w2p[NB * DH * DF / 4];   // [br][fc8][s4][h256][perm32] as uint4

static __device__ __forceinline__ uint32_t f2tf(float f) {
    uint32_t r; asm("cvt.rna.tf32.f32 %0, %1;" : "=r"(r) : "f"(f)); return r;
}

static __device__ __forceinline__ void mma8(float* c,
    uint32_t a0, uint32_t a1, uint32_t a2, uint32_t a3, uint32_t b0, uint32_t b1) {
    asm volatile("mma.sync.aligned.m16n8k8.row.col.f32.tf32.tf32.f32 "
                 "{%0,%1,%2,%3}, {%4,%5,%6,%7}, {%8,%9}, {%0,%1,%2,%3};"
                 : "+f"(c[0]), "+f"(c[1]), "+f"(c[2]), "+f"(c[3])
                 : "r"(a0), "r"(a1), "r"(a2), "r"(a3), "r"(b0), "r"(b1));
}
static __device__ __forceinline__ int permc(int col) {
    return (col & ~15) + ((col & 3) * 4) + ((col >> 2) & 3);
}

__global__ void reset_counts_kernel() {
    if (threadIdx.x < NB) g_counts[threadIdx.x] = 0;
}
__global__ void bucket_kernel(const int* __restrict__ b_seq) {
    int i = blockIdx.x * blockDim.x + threadIdx.x;
    int b = b_seq[i];
    if (b > 0) {
        int pos = atomicAdd(&g_counts[b - 1], 1);
        g_idx[(b - 1) * NTOK + pos] = i;
    }
}
__global__ void zero_kernel(const int* __restrict__ b_seq, float4* __restrict__ out) {
    int gid = blockIdx.x * blockDim.x + threadIdx.x;
    int tok = gid >> 6;
    if (b_seq[tok] == 0) out[gid] = make_float4(0.f, 0.f, 0.f, 0.f);
}

// w1 [NB][DF][DH] -> tf32 permuted fragment layout
__global__ void prep_w1_kernel(const float* __restrict__ w1) {
    int t = blockIdx.x * blockDim.x + threadIdx.x;
    int e = t * 4;
    int br = e >> 18;
    int rem = e & 262143;
    int f = rem >> 8;
    int k = rem & 255;
    float4 v = *(const float4*)(w1 + e);
    int fc = f >> 7, fl = f & 127, s = k >> 5, c = k & 31;
    uint32_t* dst = (uint32_t*)g_w1p
        + ((((br * 8 + fc) * 8 + s) * 128 + fl) << 5) + (c & 16) + ((c & 15) >> 2);
    dst[0] = f2tf(v.x); dst[4] = f2tf(v.y); dst[8] = f2tf(v.z); dst[12] = f2tf(v.w);
}
// w2 [NB][DH][DF] -> tf32 permuted fragment layout
__global__ void prep_w2_kernel(const float* __restrict__ w2) {
    int t = blockIdx.x * blockDim.x + threadIdx.x;
    int e = t * 4;
    int br = e >> 18;
    int rem = e & 262143;
    int h = rem >> 10;
    int f = rem & 1023;
    float4 v = *(const float4*)(w2 + e);
    int fc = f >> 7, s = (f >> 5) & 3, c = f & 31;
    uint32_t* dst = (uint32_t*)g_w2p
        + ((((br * 8 + fc) * 4 + s) * 256 + h) << 5) + (c & 16) + ((c & 15) >> 2);
    dst[0] = f2tf(v.x); dst[4] = f2tf(v.y); dst[8] = f2tf(v.z); dst[12] = f2tf(v.w);
}

__global__ __launch_bounds__(THREADS, 1)
void ffn_mma_kernel(const float* __restrict__ x,
                    const float* __restrict__ b1, const float* __restrict__ b2,
                    const float* __restrict__ gamma, const float* __restrict__ beta,
                    float* __restrict__ out)
{
    const int br = blockIdx.y;
    const int count = g_counts[br];
    const int t0 = blockIdx.x * TM;
    if (t0 >= count) return;

    extern __shared__ uint32_t smem[];
    int* s_tok = (int*)(smem + OFF_TOK);
    float* red = (float*)(smem + OFF_RED);
    uint32_t* Xs = smem + OFF_XS;
    uint32_t* Hs = smem + OFF_HS;

    const int tid = threadIdx.x;
    const int wid = tid >> 5, lane = tid & 31;
    const int g = lane >> 2, tig = lane & 3;
    const int wm = wid & 1, wn = wid >> 1;

    if (tid < TM) {
        int r = t0 + tid;
        s_tok[tid] = g_idx[br * NTOK + (r < count ? r : count - 1)];
    }
    __syncthreads();

    // ---- stage X tile (once), tf32 + k-permuted ----
    {
        int row = tid >> 2, q = tid & 3;
        const float4* src = (const float4*)(x + (size_t)s_tok[row] * DH) + q * 16;
        uint32_t* xr = Xs + row * XS_STRIDE + q * 64;
        #pragma unroll
        for (int j = 0; j < 16; j++) {
            float4 d = src[j];
            int grp = (j >> 2) * 16, jj = j & 3;
            xr[grp + jj]      = f2tf(d.x);
            xr[grp + 4 + jj]  = f2tf(d.y);
            xr[grp + 8 + jj]  = f2tf(d.z);
            xr[grp + 12 + jj] = f2tf(d.w);
        }
    }

    // lane-constant uint4 index parts into the permuted weight arrays
    const int c1base = ((wn * 32 + g) << 3) + tig;   // GEMM1: + s*1024 + nt*64 + k16*4
    const int c2base = ((wn * 64 + g) << 3) + tig;   // GEMM2: + s*2048 + nt*64 + k16*4
    const uint4* w1base = g_w1p + (size_t)br * 8 * 8192;
    const uint4* w2base = g_w2p + (size_t)br * 8 * 8192;

    float acc2[2][8][4];
    #pragma unroll
    for (int a = 0; a < 2; a++)
        #pragma unroll
        for (int bq = 0; bq < 8; bq++)
            #pragma unroll
            for (int cq = 0; cq < 4; cq++) acc2[a][bq][cq] = 0.f;

    __syncthreads();

    #pragma unroll 1
    for (int fc = 0; fc < 8; fc++) {
        // ================= GEMM1: C1[64x128] = X * W1chunk^T (B via LDG) =========
        float c1[2][4][4];
        #pragma unroll
        for (int a = 0; a < 2; a++)
            #pragma unroll
            for (int bq = 0; bq < 4; bq++)
                #pragma unroll
                for (int cq = 0; cq < 4; cq++) c1[a][bq][cq] = 0.f;

        const uint4* w1f = w1base + fc * 8192;
        uint4 bb1[2][4];
        #pragma unroll
        for (int nt = 0; nt < 4; nt++) bb1[0][nt] = __ldg(w1f + c1base + nt * 64);

        #pragma unroll
        for (int step = 0; step < 16; step++) {        // step = s*2 + k16
            if (step + 1 < 16) {
                int ns = (step + 1) >> 1, nk = (step + 1) & 1;
                int base = ns * 1024 + nk * 4 + c1base;
                #pragma unroll
                for (int nt = 0; nt < 4; nt++)
                    bb1[(step + 1) & 1][nt] = __ldg(w1f + base + nt * 64);
            }
            int s = step >> 1, k16 = step & 1;
            int cb = s * 32 + k16 * 16 + 4 * tig;
            uint4 aL[2], aH[2];
            #pragma unroll
            for (int mt = 0; mt < 2; mt++) {
                int r0 = wm * 32 + mt * 16 + g;
                aL[mt] = *(const uint4*)(Xs + r0 * XS_STRIDE + cb);
                aH[mt] = *(const uint4*)(Xs + (r0 + 8) * XS_STRIDE + cb);
            }
            #pragma unroll
            for (int mt = 0; mt < 2; mt++)
                #pragma unroll
                for (int nt = 0; nt < 4; nt++) {
                    const uint4 bf = bb1[step & 1][nt];
                    mma8(c1[mt][nt], aL[mt].x, aH[mt].x, aL[mt].y, aH[mt].y, bf.x, bf.y);
                    mma8(c1[mt][nt], aL[mt].z, aH[mt].z, aL[mt].w, aH[mt].w, bf.z, bf.w);
                }
        }

        // ================= bias + ELU -> Hs =================
        __syncthreads();   // previous GEMM2 reads of Hs complete
        {
            const float* b1g = b1 + br * DF + fc * 128;
            #pragma unroll
            for (int nt = 0; nt < 4; nt++) {
                int col0 = wn * 32 + nt * 8 + 2 * tig;
                float ba = b1g[col0], bb = b1g[col0 + 1];
                int pc0 = permc(col0), pc1 = permc(col0 + 1);
                #pragma unroll
                for (int mt = 0; mt < 2; mt++) {
                    int r0 = wm * 32 + mt * 16 + g;
                    float v00 = c1[mt][nt][0] + ba;
                    float v01 = c1[mt][nt][1] + bb;
                    float v10 = c1[mt][nt][2] + ba;
                    float v11 = c1[mt][nt][3] + bb;
                    v00 = v00 > 0.f ? v00 : expm1f(v00);
                    v01 = v01 > 0.f ? v01 : expm1f(v01);
                    v10 = v10 > 0.f ? v10 : expm1f(v10);
                    v11 = v11 > 0.f ? v11 : expm1f(v11);
                    Hs[r0 * HS_STRIDE + pc0] = f2tf(v00);
                    Hs[r0 * HS_STRIDE + pc1] = f2tf(v01);
                    Hs[(r0 + 8) * HS_STRIDE + pc0] = f2tf(v10);
                    Hs[(r0 + 8) * HS_STRIDE + pc1] = f2tf(v11);
                }
            }
        }
        __syncthreads();   // Hs ready for all warps

        // ================= GEMM2: acc2[64x256] += H * W2chunk^T (B via LDG) ======
        const uint4* w2f = w2base + fc * 8192;
        uint4 bb2[2][8];
        #pragma unroll
        for (int nt = 0; nt < 8; nt++) bb2[0][nt] = __ldg(w2f + c2base + nt * 64);

        #pragma unroll
        for (int step = 0; step < 8; step++) {         // step = s*2 + k16
            if (step + 1 < 8) {
                int ns = (step + 1) >> 1, nk = (step + 1) & 1;
                int base = ns * 2048 + nk * 4 + c2base;
                #pragma unroll
                for (int nt = 0; nt < 8; nt++)
                    bb2[(step + 1) & 1][nt] = __ldg(w2f + base + nt * 64);
            }
            int s = step >> 1, k16 = step & 1;
            int cb = s * 32 + k16 * 16 + 4 * tig;
            uint4 aL[2], aH[2];
            #pragma unroll
            for (int mt = 0; mt < 2; mt++) {
                int r0 = wm * 32 + mt * 16 + g;
                aL[mt] = *(const uint4*)(Hs + r0 * HS_STRIDE + cb);
                aH[mt] = *(const uint4*)(Hs + (r0 + 8) * HS_STRIDE + cb);
            }
            #pragma unroll
            for (int nt = 0; nt < 8; nt++) {
                const uint4 bf = bb2[step & 1][nt];
                #pragma unroll
                for (int mt = 0; mt < 2; mt++) {
                    mma8(acc2[mt][nt], aL[mt].x, aH[mt].x, aL[mt].y, aH[mt].y, bf.x, bf.y);
                    mma8(acc2[mt][nt], aL[mt].z, aH[mt].z, aL[mt].w, aH[mt].w, bf.z, bf.w);
                }
            }
        }
    }

    // ================= epilogue: b2 + exact LayerNorm + scatter =================
    {
        const float* b2g = b2 + br * DH;
        #pragma unroll
        for (int nt = 0; nt < 8; nt++) {
            int col0 = wn * 64 + nt * 8 + 2 * tig;
            float2 bb = *(const float2*)(b2g + col0);
            #pragma unroll
            for (int mt = 0; mt < 2; mt++) {
                acc2[mt][nt][0] += bb.x; acc2[mt][nt][1] += bb.y;
                acc2[mt][nt][2] += bb.x; acc2[mt][nt][3] += bb.y;
            }
        }
        __syncthreads();
        float mu[4], rstd[4];
        #pragma unroll
        for (int rr = 0; rr < 4; rr++) {
            int mt = rr >> 1, hi = rr & 1;
            float sfull = 0.f;
            #pragma unroll
            for (int nt = 0; nt < 8; nt++) sfull += acc2[mt][nt][hi * 2] + acc2[mt][nt][hi * 2 + 1];
            sfull += __shfl_xor_sync(0xffffffffu, sfull, 1);
            sfull += __shfl_xor_sync(0xffffffffu, sfull, 2);
            int row = wm * 32 + mt * 16 + hi * 8 + g;
            if (tig == 0) red[row * 4 + wn] = sfull;
        }
        __syncthreads();
        #pragma unroll
        for (int rr = 0; rr < 4; rr++) {
            int mt = rr >> 1, hi = rr & 1;
            int row = wm * 32 + mt * 16 + hi * 8 + g;
            mu[rr] = (red[row * 4] + red[row * 4 + 1] + red[row * 4 + 2] + red[row * 4 + 3]) * (1.f / 256.f);
        }
        __syncthreads();
        #pragma unroll
        for (int rr = 0; rr < 4; rr++) {
            int mt = rr >> 1, hi = rr & 1;
            float sq = 0.f;
            #pragma unroll
            for (int nt = 0; nt < 8; nt++) {
                float d0 = acc2[mt][nt][hi * 2] - mu[rr];
                float d1 = acc2[mt][nt][hi * 2 + 1] - mu[rr];
                sq += d0 * d0 + d1 * d1;
            }
            sq += __shfl_xor_sync(0xffffffffu, sq, 1);
            sq += __shfl_xor_sync(0xffffffffu, sq, 2);
            int row = wm * 32 + mt * 16 + hi * 8 + g;
            if (tig == 0) red[row * 4 + wn] = sq;
        }
        __syncthreads();
        #pragma unroll
        for (int rr = 0; rr < 4; rr++) {
            int mt = rr >> 1, hi = rr & 1;
            int row = wm * 32 + mt * 16 + hi * 8 + g;
            float var = (red[row * 4] + red[row * 4 + 1] + red[row * 4 + 2] + red[row * 4 + 3]) * (1.f / 256.f);
            rstd[rr] = rsqrtf(var + 1e-12f);
        }

        const float* gg = gamma + br * DH;
        const float* be = beta + br * DH;
        #pragma unroll
        for (int rr = 0; rr < 4; rr++) {
            int mt = rr >> 1, hi = rr & 1;
            int row = wm * 32 + mt * 16 + hi * 8 + g;
            if (t0 + row < count) {
                float* o = out + (size_t)s_tok[row] * DH;
                #pragma unroll
                for (int nt = 0; nt < 8; nt++) {
                    int col0 = wn * 64 + nt * 8 + 2 * tig;
                    float2 gm = *(const float2*)(gg + col0);
                    float2 bt = *(const float2*)(be + col0);
                    float2 v;
                    v.x = (acc2[mt][nt][hi * 2] - mu[rr]) * rstd[rr] * gm.x + bt.x;
                    v.y = (acc2[mt][nt][hi * 2 + 1] - mu[rr]) * rstd[rr] * gm.y + bt.y;
                    *(float2*)(o + col0) = v;
                }
            }
        }
    }
}

extern "C" void kernel_launch(void* const* d_in, const int* in_sizes, int n_in,
                              void* d_out, int out_size) {
    const float* x     = (const float*)d_in[0];
    const int*   b_seq = (const int*)d_in[1];
    const float* w1    = (const float*)d_in[2];
    const float* b1    = (const float*)d_in[3];
    const float* w2    = (const float*)d_in[4];
    const float* b2    = (const float*)d_in[5];
    const float* gamma = (const float*)d_in[6];
    const float* beta  = (const float*)d_in[7];
    float* out = (float*)d_out;

    const int smem_bytes = SMEM_U32 * 4;
    cudaFuncSetAttribute(ffn_mma_kernel, cudaFuncAttributeMaxDynamicSharedMemorySize, smem_bytes);

    reset_counts_kernel<<<1, 32>>>();
    bucket_kernel<<<NTOK / 256, 256>>>(b_seq);
    prep_w1_kernel<<<NB * DF * DH / 4 / 256, 256>>>(w1);
    prep_w2_kernel<<<NB * DH * DF / 4 / 256, 256>>>(w2);
    zero_kernel<<<(NTOK * 64) / 256, 256>>>(b_seq, (float4*)out);
    ffn_mma_kernel<<<dim3(NTOK / TM, NB), THREADS, smem_bytes>>>(x, b1, b2, gamma, beta, out);
}

// round 11
// speedup vs baseline: 5.4542x; 1.4665x over previous
#include <cuda_runtime.h>
#include <cuda_fp16.h>
#include <math.h>
#include <stdint.h>

#define NTOK 65536
#define DH 256
#define DF 1024
#define NB 4
#define TM 64
#define THREADS 256

#define XS_STRIDE 144   // u32 units; ≡16 (mod 32): conflict-free uint4 LDS phases
#define HS_STRIDE 80

// smem offsets in u32 units
#define OFF_TOK 0
#define OFF_RED 64
#define OFF_XS 320
#define OFF_HS (OFF_XS + 64 * XS_STRIDE)
#define SMEM_U32 (OFF_HS + 64 * HS_STRIDE)

__device__ int g_counts[NB];
__device__ int g_idx[NB * NTOK];
// fp16 weights in m16n8k16 fragment-permuted layout.
// Each (fc, step, f/h) cell holds 32 fp16 = 4 uint4.
__device__ uint4 g_w1h[NB * 8 * 8 * 128 * 4];   // [br][fc8][step8][f128][4 uint4]
__device__ uint4 g_w2h[NB * 8 * 4 * 256 * 4];   // [br][fc8][step4][h256][4 uint4]

static __device__ __forceinline__ void mma16(float* c,
    uint32_t a0, uint32_t a1, uint32_t a2, uint32_t a3, uint32_t b0, uint32_t b1) {
    asm volatile("mma.sync.aligned.m16n8k16.row.col.f32.f16.f16.f32 "
                 "{%0,%1,%2,%3}, {%4,%5,%6,%7}, {%8,%9}, {%0,%1,%2,%3};"
                 : "+f"(c[0]), "+f"(c[1]), "+f"(c[2]), "+f"(c[3])
                 : "r"(a0), "r"(a1), "r"(a2), "r"(a3), "r"(b0), "r"(b1));
}

// permutation within a 32-k block: element position for k
// t=(k&7)>>1, grp=(k>>4)&1, hi=(k>>3)&1, odd=k&1 -> p = t*8 + grp*4 + hi*2 + odd
static __device__ __forceinline__ int perm32(int kk) {
    return ((kk & 7) >> 1) * 8 + ((kk >> 4) & 1) * 4 + ((kk >> 3) & 1) * 2 + (kk & 1);
}

__global__ void reset_counts_kernel() {
    if (threadIdx.x < NB) g_counts[threadIdx.x] = 0;
}
__global__ void bucket_kernel(const int* __restrict__ b_seq) {
    int i = blockIdx.x * blockDim.x + threadIdx.x;
    int b = b_seq[i];
    if (b > 0) {
        int pos = atomicAdd(&g_counts[b - 1], 1);
        g_idx[(b - 1) * NTOK + pos] = i;
    }
}
__global__ void zero_kernel(const int* __restrict__ b_seq, float4* __restrict__ out) {
    int gid = blockIdx.x * blockDim.x + threadIdx.x;
    int tok = gid >> 6;
    if (b_seq[tok] == 0) out[gid] = make_float4(0.f, 0.f, 0.f, 0.f);
}

// w1 [NB][DF][DH] float -> fp16 fragment-permuted
__global__ void prep_w1_kernel(const float* __restrict__ w1) {
    int t = blockIdx.x * blockDim.x + threadIdx.x;
    int e = t * 4;
    int br = e >> 18;
    int rem = e & 262143;
    int f = rem >> 8;
    int k = rem & 255;
    float4 v = *(const float4*)(w1 + e);
    int fc = f >> 7, fl = f & 127, step = k >> 5, kk = k & 31;   // kk % 4 == 0
    int p = perm32(kk);                                           // even
    __half2* dst = (__half2*)g_w1h + (((((br * 8 + fc) * 8 + step) * 128 + fl) * 32) + p) / 2;
    dst[0] = __floats2half2_rn(v.x, v.y);
    dst[4] = __floats2half2_rn(v.z, v.w);   // k+2,k+3 -> p+8
}
// w2 [NB][DH][DF] float -> fp16 fragment-permuted
__global__ void prep_w2_kernel(const float* __restrict__ w2) {
    int t = blockIdx.x * blockDim.x + threadIdx.x;
    int e = t * 4;
    int br = e >> 18;
    int rem = e & 262143;
    int h = rem >> 10;
    int f = rem & 1023;
    float4 v = *(const float4*)(w2 + e);
    int fc = f >> 7, fl = f & 127, step = fl >> 5, kk = fl & 31;  // kk % 4 == 0
    int p = perm32(kk);
    __half2* dst = (__half2*)g_w2h + (((((br * 8 + fc) * 4 + step) * 256 + h) * 32) + p) / 2;
    dst[0] = __floats2half2_rn(v.x, v.y);
    dst[4] = __floats2half2_rn(v.z, v.w);
}

__global__ __launch_bounds__(THREADS, 1)
void ffn_mma_kernel(const float* __restrict__ x,
                    const float* __restrict__ b1, const float* __restrict__ b2,
                    const float* __restrict__ gamma, const float* __restrict__ beta,
                    float* __restrict__ out)
{
    const int br = blockIdx.y;
    const int count = g_counts[br];
    const int t0 = blockIdx.x * TM;
    if (t0 >= count) return;

    extern __shared__ uint32_t smem[];
    int* s_tok = (int*)(smem + OFF_TOK);
    float* red = (float*)(smem + OFF_RED);
    uint32_t* Xs = smem + OFF_XS;
    uint32_t* Hs = smem + OFF_HS;

    const int tid = threadIdx.x;
    const int wid = tid >> 5, lane = tid & 31;
    const int g = lane >> 2, tig = lane & 3;
    const int wm = wid & 1, wn = wid >> 1;

    if (tid < TM) {
        int r = t0 + tid;
        s_tok[tid] = g_idx[br * NTOK + (r < count ? r : count - 1)];
    }
    __syncthreads();

    // ---- stage X tile (once), fp16 + k-permuted: row = 8 blocks of 32 k (16 u32 each) ----
    {
        int row = tid >> 2, q = tid & 3;
        const float4* src = (const float4*)(x + (size_t)s_tok[row] * DH) + q * 16;
        uint32_t* xr = Xs + row * XS_STRIDE + q * 32;   // q covers 64 k = 2 blocks = 32 u32
        #pragma unroll
        for (int j = 0; j < 16; j++) {
            float4 d = src[j];
            int k0 = j * 4;                    // within this thread's 64-k span
            int block = k0 >> 5, kk = k0 & 31;
            int p = perm32(kk);
            __half2 h01 = __floats2half2_rn(d.x, d.y);
            __half2 h23 = __floats2half2_rn(d.z, d.w);
            uint32_t* dst = xr + block * 16 + (p >> 1);
            dst[0] = *(uint32_t*)&h01;
            dst[4] = *(uint32_t*)&h23;
        }
    }

    // lane-constant uint4 index parts into the permuted weight arrays
    const int c1base = ((wn * 32 + g) << 2) + tig;   // + step*512 + nt*32
    const int c2base = ((wn * 64 + g) << 2) + tig;   // + step*1024 + nt*32
    const uint4* w1base = g_w1h + (size_t)br * 8 * 4096;
    const uint4* w2base = g_w2h + (size_t)br * 8 * 4096;

    float acc2[2][8][4];
    #pragma unroll
    for (int a = 0; a < 2; a++)
        #pragma unroll
        for (int bq = 0; bq < 8; bq++)
            #pragma unroll
            for (int cq = 0; cq < 4; cq++) acc2[a][bq][cq] = 0.f;

    __syncthreads();

    #pragma unroll 1
    for (int fc = 0; fc < 8; fc++) {
        // ========== GEMM1: C1[64x128] = X * W1chunk^T, 8 steps of k=32 ==========
        float c1[2][4][4];
        #pragma unroll
        for (int a = 0; a < 2; a++)
            #pragma unroll
            for (int bq = 0; bq < 4; bq++)
                #pragma unroll
                for (int cq = 0; cq < 4; cq++) c1[a][bq][cq] = 0.f;

        const uint4* w1f = w1base + fc * 4096;
        uint4 bb1[2][4];
        #pragma unroll
        for (int nt = 0; nt < 4; nt++) bb1[0][nt] = __ldg(w1f + c1base + nt * 32);

        #pragma unroll
        for (int step = 0; step < 8; step++) {
            if (step + 1 < 8) {
                int base = (step + 1) * 512 + c1base;
                #pragma unroll
                for (int nt = 0; nt < 4; nt++)
                    bb1[(step + 1) & 1][nt] = __ldg(w1f + base + nt * 32);
            }
            int cb = step * 16 + 4 * tig;
            uint4 aL[2], aH[2];
            #pragma unroll
            for (int mt = 0; mt < 2; mt++) {
                int r0 = wm * 32 + mt * 16 + g;
                aL[mt] = *(const uint4*)(Xs + r0 * XS_STRIDE + cb);
                aH[mt] = *(const uint4*)(Xs + (r0 + 8) * XS_STRIDE + cb);
            }
            #pragma unroll
            for (int mt = 0; mt < 2; mt++)
                #pragma unroll
                for (int nt = 0; nt < 4; nt++) {
                    const uint4 bf = bb1[step & 1][nt];
                    mma16(c1[mt][nt], aL[mt].x, aH[mt].x, aL[mt].y, aH[mt].y, bf.x, bf.y);
                    mma16(c1[mt][nt], aL[mt].z, aH[mt].z, aL[mt].w, aH[mt].w, bf.z, bf.w);
                }
        }

        // ========== bias + ELU -> Hs (fp16, permuted) ==========
        __syncthreads();   // previous GEMM2 reads of Hs complete
        {
            const float* b1g = b1 + br * DF + fc * 128;
            #pragma unroll
            for (int nt = 0; nt < 4; nt++) {
                int col0 = wn * 32 + nt * 8 + 2 * tig;
                float ba = b1g[col0], bb = b1g[col0 + 1];
                int block = col0 >> 5;
                int p = perm32(col0 & 31);          // even
                int uoff = block * 16 + (p >> 1);
                #pragma unroll
                for (int mt = 0; mt < 2; mt++) {
                    int r0 = wm * 32 + mt * 16 + g;
                    float v00 = c1[mt][nt][0] + ba;
                    float v01 = c1[mt][nt][1] + bb;
                    float v10 = c1[mt][nt][2] + ba;
                    float v11 = c1[mt][nt][3] + bb;
                    v00 = v00 > 0.f ? v00 : expm1f(v00);
                    v01 = v01 > 0.f ? v01 : expm1f(v01);
                    v10 = v10 > 0.f ? v10 : expm1f(v10);
                    v11 = v11 > 0.f ? v11 : expm1f(v11);
                    __half2 hlo = __floats2half2_rn(v00, v01);
                    __half2 hhi = __floats2half2_rn(v10, v11);
                    Hs[r0 * HS_STRIDE + uoff] = *(uint32_t*)&hlo;
                    Hs[(r0 + 8) * HS_STRIDE + uoff] = *(uint32_t*)&hhi;
                }
            }
        }
        __syncthreads();   // Hs ready for all warps

        // ========== GEMM2: acc2[64x256] += H * W2chunk^T, 4 steps of k=32 ==========
        const uint4* w2f = w2base + fc * 4096;
        uint4 bb2[2][8];
        #pragma unroll
        for (int nt = 0; nt < 8; nt++) bb2[0][nt] = __ldg(w2f + c2base + nt * 32);

        #pragma unroll
        for (int step = 0; step < 4; step++) {
            if (step + 1 < 4) {
                int base = (step + 1) * 1024 + c2base;
                #pragma unroll
                for (int nt = 0; nt < 8; nt++)
                    bb2[(step + 1) & 1][nt] = __ldg(w2f + base + nt * 32);
            }
            int cb = step * 16 + 4 * tig;
            uint4 aL[2], aH[2];
            #pragma unroll
            for (int mt = 0; mt < 2; mt++) {
                int r0 = wm * 32 + mt * 16 + g;
                aL[mt] = *(const uint4*)(Hs + r0 * HS_STRIDE + cb);
                aH[mt] = *(const uint4*)(Hs + (r0 + 8) * HS_STRIDE + cb);
            }
            #pragma unroll
            for (int nt = 0; nt < 8; nt++) {
                const uint4 bf = bb2[step & 1][nt];
                #pragma unroll
                for (int mt = 0; mt < 2; mt++) {
                    mma16(acc2[mt][nt], aL[mt].x, aH[mt].x, aL[mt].y, aH[mt].y, bf.x, bf.y);
                    mma16(acc2[mt][nt], aL[mt].z, aH[mt].z, aL[mt].w, aH[mt].w, bf.z, bf.w);
                }
            }
        }
    }

    // ================= epilogue: b2 + exact LayerNorm + scatter =================
    {
        const float* b2g = b2 + br * DH;
        #pragma unroll
        for (int nt = 0; nt < 8; nt++) {
            int col0 = wn * 64 + nt * 8 + 2 * tig;
            float2 bb = *(const float2*)(b2g + col0);
            #pragma unroll
            for (int mt = 0; mt < 2; mt++) {
                acc2[mt][nt][0] += bb.x; acc2[mt][nt][1] += bb.y;
                acc2[mt][nt][2] += bb.x; acc2[mt][nt][3] += bb.y;
            }
        }
        __syncthreads();
        float mu[4], rstd[4];
        #pragma unroll
        for (int rr = 0; rr < 4; rr++) {
            int mt = rr >> 1, hi = rr & 1;
            float sfull = 0.f;
            #pragma unroll
            for (int nt = 0; nt < 8; nt++) sfull += acc2[mt][nt][hi * 2] + acc2[mt][nt][hi * 2 + 1];
            sfull += __shfl_xor_sync(0xffffffffu, sfull, 1);
            sfull += __shfl_xor_sync(0xffffffffu, sfull, 2);
            int row = wm * 32 + mt * 16 + hi * 8 + g;
            if (tig == 0) red[row * 4 + wn] = sfull;
        }
        __syncthreads();
        #pragma unroll
        for (int rr = 0; rr < 4; rr++) {
            int mt = rr >> 1, hi = rr & 1;
            int row = wm * 32 + mt * 16 + hi * 8 + g;
            mu[rr] = (red[row * 4] + red[row * 4 + 1] + red[row * 4 + 2] + red[row * 4 + 3]) * (1.f / 256.f);
        }
        __syncthreads();
        #pragma unroll
        for (int rr = 0; rr < 4; rr++) {
            int mt = rr >> 1, hi = rr & 1;
            float sq = 0.f;
            #pragma unroll
            for (int nt = 0; nt < 8; nt++) {
                float d0 = acc2[mt][nt][hi * 2] - mu[rr];
                float d1 = acc2[mt][nt][hi * 2 + 1] - mu[rr];
                sq += d0 * d0 + d1 * d1;
            }
            sq += __shfl_xor_sync(0xffffffffu, sq, 1);
            sq += __shfl_xor_sync(0xffffffffu, sq, 2);
            int row = wm * 32 + mt * 16 + hi * 8 + g;
            if (tig == 0) red[row * 4 + wn] = sq;
        }
        __syncthreads();
        #pragma unroll
        for (int rr = 0; rr < 4; rr++) {
            int mt = rr >> 1, hi = rr & 1;
            int row = wm * 32 + mt * 16 + hi * 8 + g;
            float var = (red[row * 4] + red[row * 4 + 1] + red[row * 4 + 2] + red[row * 4 + 3]) * (1.f / 256.f);
            rstd[rr] = rsqrtf(var + 1e-12f);
        }

        const float* gg = gamma + br * DH;
        const float* be = beta + br * DH;
        #pragma unroll
        for (int rr = 0; rr < 4; rr++) {
            int mt = rr >> 1, hi = rr & 1;
            int row = wm * 32 + mt * 16 + hi * 8 + g;
            if (t0 + row < count) {
                float* o = out + (size_t)s_tok[row] * DH;
                #pragma unroll
                for (int nt = 0; nt < 8; nt++) {
                    int col0 = wn * 64 + nt * 8 + 2 * tig;
                    float2 gm = *(const float2*)(gg + col0);
                    float2 bt = *(const float2*)(be + col0);
                    float2 v;
                    v.x = (acc2[mt][nt][hi * 2] - mu[rr]) * rstd[rr] * gm.x + bt.x;
                    v.y = (acc2[mt][nt][hi * 2 + 1] - mu[rr]) * rstd[rr] * gm.y + bt.y;
                    *(float2*)(o + col0) = v;
                }
            }
        }
    }
}

extern "C" void kernel_launch(void* const* d_in, const int* in_sizes, int n_in,
                              void* d_out, int out_size) {
    const float* x     = (const float*)d_in[0];
    const int*   b_seq = (const int*)d_in[1];
    const float* w1    = (const float*)d_in[2];
    const float* b1    = (const float*)d_in[3];
    const float* w2    = (const float*)d_in[4];
    const float* b2    = (const float*)d_in[5];
    const float* gamma = (const float*)d_in[6];
    const float* beta  = (const float*)d_in[7];
    float* out = (float*)d_out;

    const int smem_bytes = SMEM_U32 * 4;
    cudaFuncSetAttribute(ffn_mma_kernel, cudaFuncAttributeMaxDynamicSharedMemorySize, smem_bytes);

    reset_counts_kernel<<<1, 32>>>();
    bucket_kernel<<<NTOK / 256, 256>>>(b_seq);
    prep_w1_kernel<<<NB * DF * DH / 4 / 256, 256>>>(w1);
    prep_w2_kernel<<<NB * DH * DF / 4 / 256, 256>>>(w2);
    zero_kernel<<<(NTOK * 64) / 256, 256>>>(b_seq, (float4*)out);
    ffn_mma_kernel<<<dim3(NTOK / TM, NB), THREADS, smem_bytes>>>(x, b1, b2, gamma, beta, out);
}

// round 12
// speedup vs baseline: 6.1290x; 1.1237x over previous
#include <cuda_runtime.h>
#include <cuda_fp16.h>
#include <math.h>
#include <stdint.h>

#define NTOK 65536
#define DH 256
#define DF 1024
#define NB 4
#define TM 64
#define THREADS 512

#define XS_STRIDE 144   // u32 units; ≡16 (mod 32): conflict-free uint4 LDS phases
#define HS_STRIDE 80

// smem offsets in u32 units
#define OFF_TOK 0
#define OFF_RED 64                 // 64 rows x 8 warp-partials
#define OFF_XS 576
#define OFF_HS (OFF_XS + 64 * XS_STRIDE)
#define SMEM_U32 (OFF_HS + 64 * HS_STRIDE)

__device__ int g_counts[NB];
__device__ int g_idx[NB * NTOK];
// fp16 weights in m16n8k16 fragment-permuted layout.
// Each (fc, step, f/h) cell holds 32 fp16 = 4 uint4.
__device__ uint4 g_w1h[NB * 8 * 8 * 128 * 4];   // [br][fc8][step8][f128][4 uint4]
__device__ uint4 g_w2h[NB * 8 * 4 * 256 * 4];   // [br][fc8][step4][h256][4 uint4]

static __device__ __forceinline__ void mma16(float* c,
    uint32_t a0, uint32_t a1, uint32_t a2, uint32_t a3, uint32_t b0, uint32_t b1) {
    asm volatile("mma.sync.aligned.m16n8k16.row.col.f32.f16.f16.f32 "
                 "{%0,%1,%2,%3}, {%4,%5,%6,%7}, {%8,%9}, {%0,%1,%2,%3};"
                 : "+f"(c[0]), "+f"(c[1]), "+f"(c[2]), "+f"(c[3])
                 : "r"(a0), "r"(a1), "r"(a2), "r"(a3), "r"(b0), "r"(b1));
}

// permutation within a 32-k block: element position for k
// t=(k&7)>>1, grp=(k>>4)&1, hi=(k>>3)&1, odd=k&1 -> p = t*8 + grp*4 + hi*2 + odd
static __device__ __forceinline__ int perm32(int kk) {
    return ((kk & 7) >> 1) * 8 + ((kk >> 4) & 1) * 4 + ((kk >> 3) & 1) * 2 + (kk & 1);
}

__global__ void reset_counts_kernel() {
    if (threadIdx.x < NB) g_counts[threadIdx.x] = 0;
}
__global__ void bucket_kernel(const int* __restrict__ b_seq) {
    int i = blockIdx.x * blockDim.x + threadIdx.x;
    int b = b_seq[i];
    if (b > 0) {
        int pos = atomicAdd(&g_counts[b - 1], 1);
        g_idx[(b - 1) * NTOK + pos] = i;
    }
}
__global__ void zero_kernel(const int* __restrict__ b_seq, float4* __restrict__ out) {
    int gid = blockIdx.x * blockDim.x + threadIdx.x;
    int tok = gid >> 6;
    if (b_seq[tok] == 0) out[gid] = make_float4(0.f, 0.f, 0.f, 0.f);
}

// w1 [NB][DF][DH] float -> fp16 fragment-permuted
__global__ void prep_w1_kernel(const float* __restrict__ w1) {
    int t = blockIdx.x * blockDim.x + threadIdx.x;
    int e = t * 4;
    int br = e >> 18;
    int rem = e & 262143;
    int f = rem >> 8;
    int k = rem & 255;
    float4 v = *(const float4*)(w1 + e);
    int fc = f >> 7, fl = f & 127, step = k >> 5, kk = k & 31;   // kk % 4 == 0
    int p = perm32(kk);                                           // even
    __half2* dst = (__half2*)g_w1h + (((((br * 8 + fc) * 8 + step) * 128 + fl) * 32) + p) / 2;
    dst[0] = __floats2half2_rn(v.x, v.y);
    dst[4] = __floats2half2_rn(v.z, v.w);   // k+2,k+3 -> p+8
}
// w2 [NB][DH][DF] float -> fp16 fragment-permuted
__global__ void prep_w2_kernel(const float* __restrict__ w2) {
    int t = blockIdx.x * blockDim.x + threadIdx.x;
    int e = t * 4;
    int br = e >> 18;
    int rem = e & 262143;
    int h = rem >> 10;
    int f = rem & 1023;
    float4 v = *(const float4*)(w2 + e);
    int fc = f >> 7, fl = f & 127, step = fl >> 5, kk = fl & 31;  // kk % 4 == 0
    int p = perm32(kk);
    __half2* dst = (__half2*)g_w2h + (((((br * 8 + fc) * 4 + step) * 256 + h) * 32) + p) / 2;
    dst[0] = __floats2half2_rn(v.x, v.y);
    dst[4] = __floats2half2_rn(v.z, v.w);
}

__global__ __launch_bounds__(THREADS, 1)
void ffn_mma_kernel(const float* __restrict__ x,
                    const float* __restrict__ b1, const float* __restrict__ b2,
                    const float* __restrict__ gamma, const float* __restrict__ beta,
                    float* __restrict__ out)
{
    const int br = blockIdx.y;
    const int count = g_counts[br];
    const int t0 = blockIdx.x * TM;
    if (t0 >= count) return;

    extern __shared__ uint32_t smem[];
    int* s_tok = (int*)(smem + OFF_TOK);
    float* red = (float*)(smem + OFF_RED);
    uint32_t* Xs = smem + OFF_XS;
    uint32_t* Hs = smem + OFF_HS;

    const int tid = threadIdx.x;
    const int wid = tid >> 5, lane = tid & 31;
    const int g = lane >> 2, tig = lane & 3;
    const int wm = wid & 1, wn = wid >> 1;   // 2 m-warps x 8 n-warps

    if (tid < TM) {
        int r = t0 + tid;
        s_tok[tid] = g_idx[br * NTOK + (r < count ? r : count - 1)];
    }
    __syncthreads();

    // ---- stage X tile (once), fp16 + k-permuted: 8 threads/row, one 32-k block each ----
    {
        int row = tid >> 3, q = tid & 7;
        const float4* src = (const float4*)(x + (size_t)s_tok[row] * DH) + q * 8;
        uint32_t* xr = Xs + row * XS_STRIDE + q * 16;
        #pragma unroll
        for (int j = 0; j < 8; j++) {
            float4 d = src[j];
            int p = perm32(j * 4);
            __half2 h01 = __floats2half2_rn(d.x, d.y);
            __half2 h23 = __floats2half2_rn(d.z, d.w);
            uint32_t* dst = xr + (p >> 1);
            dst[0] = *(uint32_t*)&h01;
            dst[4] = *(uint32_t*)&h23;
        }
    }

    // lane-constant uint4 index parts into the permuted weight arrays
    const int c1base = ((wn * 16 + g) << 2) + tig;   // + step*512 + nt*32
    const int c2base = ((wn * 32 + g) << 2) + tig;   // + step*1024 + nt*32
    const uint4* w1base = g_w1h + (size_t)br * 8 * 4096;
    const uint4* w2base = g_w2h + (size_t)br * 8 * 4096;

    float acc2[2][4][4];
    #pragma unroll
    for (int a = 0; a < 2; a++)
        #pragma unroll
        for (int bq = 0; bq < 4; bq++)
            #pragma unroll
            for (int cq = 0; cq < 4; cq++) acc2[a][bq][cq] = 0.f;

    __syncthreads();

    #pragma unroll 1
    for (int fc = 0; fc < 8; fc++) {
        // ========== GEMM1: C1[64x128] = X * W1chunk^T, 8 steps of k=32 ==========
        float c1[2][2][4];
        #pragma unroll
        for (int a = 0; a < 2; a++)
            #pragma unroll
            for (int bq = 0; bq < 2; bq++)
                #pragma unroll
                for (int cq = 0; cq < 4; cq++) c1[a][bq][cq] = 0.f;

        const uint4* w1f = w1base + fc * 4096;
        uint4 bb1[2][2];
        #pragma unroll
        for (int nt = 0; nt < 2; nt++) bb1[0][nt] = __ldg(w1f + c1base + nt * 32);

        #pragma unroll
        for (int step = 0; step < 8; step++) {
            if (step + 1 < 8) {
                int base = (step + 1) * 512 + c1base;
                #pragma unroll
                for (int nt = 0; nt < 2; nt++)
                    bb1[(step + 1) & 1][nt] = __ldg(w1f + base + nt * 32);
            }
            int cb = step * 16 + 4 * tig;
            uint4 aL[2], aH[2];
            #pragma unroll
            for (int mt = 0; mt < 2; mt++) {
                int r0 = wm * 32 + mt * 16 + g;
                aL[mt] = *(const uint4*)(Xs + r0 * XS_STRIDE + cb);
                aH[mt] = *(const uint4*)(Xs + (r0 + 8) * XS_STRIDE + cb);
            }
            #pragma unroll
            for (int mt = 0; mt < 2; mt++)
                #pragma unroll
                for (int nt = 0; nt < 2; nt++) {
                    const uint4 bf = bb1[step & 1][nt];
                    mma16(c1[mt][nt], aL[mt].x, aH[mt].x, aL[mt].y, aH[mt].y, bf.x, bf.y);
                    mma16(c1[mt][nt], aL[mt].z, aH[mt].z, aL[mt].w, aH[mt].w, bf.z, bf.w);
                }
        }

        // ========== bias + ELU -> Hs (fp16, permuted) ==========
        __syncthreads();   // previous GEMM2 reads of Hs complete
        {
            const float* b1g = b1 + br * DF + fc * 128;
            #pragma unroll
            for (int nt = 0; nt < 2; nt++) {
                int col0 = wn * 16 + nt * 8 + 2 * tig;
                float ba = b1g[col0], bb = b1g[col0 + 1];
                int block = col0 >> 5;
                int p = perm32(col0 & 31);          // even
                int uoff = block * 16 + (p >> 1);
                #pragma unroll
                for (int mt = 0; mt < 2; mt++) {
                    int r0 = wm * 32 + mt * 16 + g;
                    float v00 = c1[mt][nt][0] + ba;
                    float v01 = c1[mt][nt][1] + bb;
                    float v10 = c1[mt][nt][2] + ba;
                    float v11 = c1[mt][nt][3] + bb;
                    v00 = v00 > 0.f ? v00 : expm1f(v00);
                    v01 = v01 > 0.f ? v01 : expm1f(v01);
                    v10 = v10 > 0.f ? v10 : expm1f(v10);
                    v11 = v11 > 0.f ? v11 : expm1f(v11);
                    __half2 hlo = __floats2half2_rn(v00, v01);
                    __half2 hhi = __floats2half2_rn(v10, v11);
                    Hs[r0 * HS_STRIDE + uoff] = *(uint32_t*)&hlo;
                    Hs[(r0 + 8) * HS_STRIDE + uoff] = *(uint32_t*)&hhi;
                }
            }
        }
        __syncthreads();   // Hs ready for all warps

        // ========== GEMM2: acc2[64x256] += H * W2chunk^T, 4 steps of k=32 ==========
        const uint4* w2f = w2base + fc * 4096;
        uint4 bb2[4];
        #pragma unroll
        for (int nt = 0; nt < 4; nt++) bb2[nt] = __ldg(w2f + c2base + nt * 32);

        #pragma unroll
        for (int step = 0; step < 4; step++) {
            int cb = step * 16 + 4 * tig;
            uint4 aL[2], aH[2];
            #pragma unroll
            for (int mt = 0; mt < 2; mt++) {
                int r0 = wm * 32 + mt * 16 + g;
                aL[mt] = *(const uint4*)(Hs + r0 * HS_STRIDE + cb);
                aH[mt] = *(const uint4*)(Hs + (r0 + 8) * HS_STRIDE + cb);
            }
            #pragma unroll
            for (int nt = 0; nt < 4; nt++) {
                const uint4 bf = bb2[nt];
                #pragma unroll
                for (int mt = 0; mt < 2; mt++) {
                    mma16(acc2[mt][nt], aL[mt].x, aH[mt].x, aL[mt].y, aH[mt].y, bf.x, bf.y);
                    mma16(acc2[mt][nt], aL[mt].z, aH[mt].z, aL[mt].w, aH[mt].w, bf.z, bf.w);
                }
            }
            if (step + 1 < 4) {   // tail prefetch into same regs (WAR-safe: after mma issue)
                int base = (step + 1) * 1024 + c2base;
                #pragma unroll
                for (int nt = 0; nt < 4; nt++)
                    bb2[nt] = __ldg(w2f + base + nt * 32);
            }
        }
    }

    // ================= epilogue: b2 + exact LayerNorm + scatter =================
    {
        const float* b2g = b2 + br * DH;
        #pragma unroll
        for (int nt = 0; nt < 4; nt++) {
            int col0 = wn * 32 + nt * 8 + 2 * tig;
            float2 bb = *(const float2*)(b2g + col0);
            #pragma unroll
            for (int mt = 0; mt < 2; mt++) {
                acc2[mt][nt][0] += bb.x; acc2[mt][nt][1] += bb.y;
                acc2[mt][nt][2] += bb.x; acc2[mt][nt][3] += bb.y;
            }
        }
        __syncthreads();
        float mu[4], rstd[4];
        #pragma unroll
        for (int rr = 0; rr < 4; rr++) {
            int mt = rr >> 1, hi = rr & 1;
            float sfull = 0.f;
            #pragma unroll
            for (int nt = 0; nt < 4; nt++) sfull += acc2[mt][nt][hi * 2] + acc2[mt][nt][hi * 2 + 1];
            sfull += __shfl_xor_sync(0xffffffffu, sfull, 1);
            sfull += __shfl_xor_sync(0xffffffffu, sfull, 2);
            int row = wm * 32 + mt * 16 + hi * 8 + g;
            if (tig == 0) red[row * 8 + wn] = sfull;
        }
        __syncthreads();
        #pragma unroll
        for (int rr = 0; rr < 4; rr++) {
            int mt = rr >> 1, hi = rr & 1;
            int row = wm * 32 + mt * 16 + hi * 8 + g;
            float s = 0.f;
            #pragma unroll
            for (int w = 0; w < 8; w++) s += red[row * 8 + w];
            mu[rr] = s * (1.f / 256.f);
        }
        __syncthreads();
        #pragma unroll
        for (int rr = 0; rr < 4; rr++) {
            int mt = rr >> 1, hi = rr & 1;
            float sq = 0.f;
            #pragma unroll
            for (int nt = 0; nt < 4; nt++) {
                float d0 = acc2[mt][nt][hi * 2] - mu[rr];
                float d1 = acc2[mt][nt][hi * 2 + 1] - mu[rr];
                sq += d0 * d0 + d1 * d1;
            }
            sq += __shfl_xor_sync(0xffffffffu, sq, 1);
            sq += __shfl_xor_sync(0xffffffffu, sq, 2);
            int row = wm * 32 + mt * 16 + hi * 8 + g;
            if (tig == 0) red[row * 8 + wn] = sq;
        }
        __syncthreads();
        #pragma unroll
        for (int rr = 0; rr < 4; rr++) {
            int mt = rr >> 1, hi = rr & 1;
            int row = wm * 32 + mt * 16 + hi * 8 + g;
            float s = 0.f;
            #pragma unroll
            for (int w = 0; w < 8; w++) s += red[row * 8 + w];
            rstd[rr] = rsqrtf(s * (1.f / 256.f) + 1e-12f);
        }

        const float* gg = gamma + br * DH;
        const float* be = beta + br * DH;
        #pragma unroll
        for (int rr = 0; rr < 4; rr++) {
            int mt = rr >> 1, hi = rr & 1;
            int row = wm * 32 + mt * 16 + hi * 8 + g;
            if (t0 + row < count) {
                float* o = out + (size_t)s_tok[row] * DH;
                #pragma unroll
                for (int nt = 0; nt < 4; nt++) {
                    int col0 = wn * 32 + nt * 8 + 2 * tig;
                    float2 gm = *(const float2*)(gg + col0);
                    float2 bt = *(const float2*)(be + col0);
                    float2 v;
                    v.x = (acc2[mt][nt][hi * 2] - mu[rr]) * rstd[rr] * gm.x + bt.x;
                    v.y = (acc2[mt][nt][hi * 2 + 1] - mu[rr]) * rstd[rr] * gm.y + bt.y;
                    *(float2*)(o + col0) = v;
                }
            }
        }
    }
}

extern "C" void kernel_launch(void* const* d_in, const int* in_sizes, int n_in,
                              void* d_out, int out_size) {
    const float* x     = (const float*)d_in[0];
    const int*   b_seq = (const int*)d_in[1];
    const float* w1    = (const float*)d_in[2];
    const float* b1    = (const float*)d_in[3];
    const float* w2    = (const float*)d_in[4];
    const float* b2    = (const float*)d_in[5];
    const float* gamma = (const float*)d_in[6];
    const float* beta  = (const float*)d_in[7];
    float* out = (float*)d_out;

    const int smem_bytes = SMEM_U32 * 4;
    cudaFuncSetAttribute(ffn_mma_kernel, cudaFuncAttributeMaxDynamicSharedMemorySize, smem_bytes);

    reset_counts_kernel<<<1, 32>>>();
    bucket_kernel<<<NTOK / 256, 256>>>(b_seq);
    prep_w1_kernel<<<NB * DF * DH / 4 / 256, 256>>>(w1);
    prep_w2_kernel<<<NB * DH * DF / 4 / 256, 256>>>(w2);
    zero_kernel<<<(NTOK * 64) / 256, 256>>>(b_seq, (float4*)out);
    ffn_mma_kernel<<<dim3(NTOK / TM, NB), THREADS, smem_bytes>>>(x, b1, b2, gamma, beta, out);
}

// round 13
// speedup vs baseline: 6.9927x; 1.1409x over previous
#include <cuda_runtime.h>
#include <cuda_fp16.h>
#include <math.h>
#include <stdint.h>

#define NTOK 65536
#define DH 256
#define DF 1024
#define NB 4
#define TM 64
#define THREADS 512

#define XS_STRIDE 144   // u32 units; ≡16 (mod 32): conflict-free uint4 LDS phases
#define HS_STRIDE 80
#define HS_BUF (64 * HS_STRIDE)

// smem offsets in u32 units
#define OFF_TOK 0
#define OFF_RED 64                 // 64 rows x 8 warp-partials
#define OFF_XS 576
#define OFF_HS (OFF_XS + 64 * XS_STRIDE)
#define SMEM_U32 (OFF_HS + 2 * HS_BUF)

__device__ int g_counts[NB];
__device__ int g_idx[NB * NTOK];
// fp16 weights in m16n8k16 fragment-permuted layout.
// Each (fc, step, f/h) cell holds 32 fp16 = 4 uint4.
__device__ uint4 g_w1h[NB * 8 * 8 * 128 * 4];   // [br][fc8][step8][f128][4 uint4]
__device__ uint4 g_w2h[NB * 8 * 4 * 256 * 4];   // [br][fc8][step4][h256][4 uint4]

static __device__ __forceinline__ void mma16(float* c,
    uint32_t a0, uint32_t a1, uint32_t a2, uint32_t a3, uint32_t b0, uint32_t b1) {
    asm volatile("mma.sync.aligned.m16n8k16.row.col.f32.f16.f16.f32 "
                 "{%0,%1,%2,%3}, {%4,%5,%6,%7}, {%8,%9}, {%0,%1,%2,%3};"
                 : "+f"(c[0]), "+f"(c[1]), "+f"(c[2]), "+f"(c[3])
                 : "r"(a0), "r"(a1), "r"(a2), "r"(a3), "r"(b0), "r"(b1));
}

// fast ELU: abs error ~5e-7 near 0 (<< fp16 rounding of H)
static __device__ __forceinline__ float elu_fast(float v) {
    return v > 0.f ? v : (__expf(v) - 1.f);
}

// permutation within a 32-k block: element position for k
// t=(k&7)>>1, grp=(k>>4)&1, hi=(k>>3)&1, odd=k&1 -> p = t*8 + grp*4 + hi*2 + odd
static __device__ __forceinline__ int perm32(int kk) {
    return ((kk & 7) >> 1) * 8 + ((kk >> 4) & 1) * 4 + ((kk >> 3) & 1) * 2 + (kk & 1);
}

__global__ void reset_counts_kernel() {
    if (threadIdx.x < NB) g_counts[threadIdx.x] = 0;
}
__global__ void bucket_kernel(const int* __restrict__ b_seq) {
    int i = blockIdx.x * blockDim.x + threadIdx.x;
    int b = b_seq[i];
    if (b > 0) {
        int pos = atomicAdd(&g_counts[b - 1], 1);
        g_idx[(b - 1) * NTOK + pos] = i;
    }
}
__global__ void zero_kernel(const int* __restrict__ b_seq, float4* __restrict__ out) {
    int gid = blockIdx.x * blockDim.x + threadIdx.x;
    int tok = gid >> 6;
    if (b_seq[tok] == 0) out[gid] = make_float4(0.f, 0.f, 0.f, 0.f);
}

// w1 [NB][DF][DH] float -> fp16 fragment-permuted
__global__ void prep_w1_kernel(const float* __restrict__ w1) {
    int t = blockIdx.x * blockDim.x + threadIdx.x;
    int e = t * 4;
    int br = e >> 18;
    int rem = e & 262143;
    int f = rem >> 8;
    int k = rem & 255;
    float4 v = *(const float4*)(w1 + e);
    int fc = f >> 7, fl = f & 127, step = k >> 5, kk = k & 31;   // kk % 4 == 0
    int p = perm32(kk);                                           // even
    __half2* dst = (__half2*)g_w1h + (((((br * 8 + fc) * 8 + step) * 128 + fl) * 32) + p) / 2;
    dst[0] = __floats2half2_rn(v.x, v.y);
    dst[4] = __floats2half2_rn(v.z, v.w);   // k+2,k+3 -> p+8
}
// w2 [NB][DH][DF] float -> fp16 fragment-permuted
__global__ void prep_w2_kernel(const float* __restrict__ w2) {
    int t = blockIdx.x * blockDim.x + threadIdx.x;
    int e = t * 4;
    int br = e >> 18;
    int rem = e & 262143;
    int h = rem >> 10;
    int f = rem & 1023;
    float4 v = *(const float4*)(w2 + e);
    int fc = f >> 7, fl = f & 127, step = fl >> 5, kk = fl & 31;  // kk % 4 == 0
    int p = perm32(kk);
    __half2* dst = (__half2*)g_w2h + (((((br * 8 + fc) * 4 + step) * 256 + h) * 32) + p) / 2;
    dst[0] = __floats2half2_rn(v.x, v.y);
    dst[4] = __floats2half2_rn(v.z, v.w);
}

__global__ __launch_bounds__(THREADS, 1)
void ffn_mma_kernel(const float* __restrict__ x,
                    const float* __restrict__ b1, const float* __restrict__ b2,
                    const float* __restrict__ gamma, const float* __restrict__ beta,
                    float* __restrict__ out)
{
    const int br = blockIdx.y;
    const int count = g_counts[br];
    const int t0 = blockIdx.x * TM;
    if (t0 >= count) return;

    extern __shared__ uint32_t smem[];
    int* s_tok = (int*)(smem + OFF_TOK);
    float* red = (float*)(smem + OFF_RED);
    uint32_t* Xs = smem + OFF_XS;

    const int tid = threadIdx.x;
    const int wid = tid >> 5, lane = tid & 31;
    const int g = lane >> 2, tig = lane & 3;
    const int wm = wid & 1, wn = wid >> 1;   // 2 m-warps x 8 n-warps

    if (tid < TM) {
        int r = t0 + tid;
        s_tok[tid] = g_idx[br * NTOK + (r < count ? r : count - 1)];
    }
    __syncthreads();

    // ---- stage X tile (once), fp16 + k-permuted: 8 threads/row, one 32-k block each ----
    {
        int row = tid >> 3, q = tid & 7;
        const float4* src = (const float4*)(x + (size_t)s_tok[row] * DH) + q * 8;
        uint32_t* xr = Xs + row * XS_STRIDE + q * 16;
        #pragma unroll
        for (int j = 0; j < 8; j++) {
            float4 d = src[j];
            int p = perm32(j * 4);
            __half2 h01 = __floats2half2_rn(d.x, d.y);
            __half2 h23 = __floats2half2_rn(d.z, d.w);
            uint32_t* dst = xr + (p >> 1);
            dst[0] = *(uint32_t*)&h01;
            dst[4] = *(uint32_t*)&h23;
        }
    }

    // lane-constant uint4 index parts into the permuted weight arrays
    const int c1base = ((wn * 16 + g) << 2) + tig;   // + step*512 + nt*32
    const int c2base = ((wn * 32 + g) << 2) + tig;   // + step*1024 + nt*32
    const uint4* w1base = g_w1h + (size_t)br * 8 * 4096;
    const uint4* w2base = g_w2h + (size_t)br * 8 * 4096;

    float acc2[2][4][4];
    #pragma unroll
    for (int a = 0; a < 2; a++)
        #pragma unroll
        for (int bq = 0; bq < 4; bq++)
            #pragma unroll
            for (int cq = 0; cq < 4; cq++) acc2[a][bq][cq] = 0.f;

    __syncthreads();

    #pragma unroll 1
    for (int fc = 0; fc < 8; fc++) {
        uint32_t* Hs = smem + OFF_HS + (fc & 1) * HS_BUF;

        // ========== GEMM1: C1[64x128] = X * W1chunk^T, 8 steps of k=32 ==========
        float c1[2][2][4];
        #pragma unroll
        for (int a = 0; a < 2; a++)
            #pragma unroll
            for (int bq = 0; bq < 2; bq++)
                #pragma unroll
                for (int cq = 0; cq < 4; cq++) c1[a][bq][cq] = 0.f;

        const uint4* w1f = w1base + fc * 4096;
        uint4 bb1[2][2];
        #pragma unroll
        for (int nt = 0; nt < 2; nt++) bb1[0][nt] = __ldg(w1f + c1base + nt * 32);

        #pragma unroll
        for (int step = 0; step < 8; step++) {
            if (step + 1 < 8) {
                int base = (step + 1) * 512 + c1base;
                #pragma unroll
                for (int nt = 0; nt < 2; nt++)
                    bb1[(step + 1) & 1][nt] = __ldg(w1f + base + nt * 32);
            }
            int cb = step * 16 + 4 * tig;
            uint4 aL[2], aH[2];
            #pragma unroll
            for (int mt = 0; mt < 2; mt++) {
                int r0 = wm * 32 + mt * 16 + g;
                aL[mt] = *(const uint4*)(Xs + r0 * XS_STRIDE + cb);
                aH[mt] = *(const uint4*)(Xs + (r0 + 8) * XS_STRIDE + cb);
            }
            #pragma unroll
            for (int mt = 0; mt < 2; mt++)
                #pragma unroll
                for (int nt = 0; nt < 2; nt++) {
                    const uint4 bf = bb1[step & 1][nt];
                    mma16(c1[mt][nt], aL[mt].x, aH[mt].x, aL[mt].y, aH[mt].y, bf.x, bf.y);
                    mma16(c1[mt][nt], aL[mt].z, aH[mt].z, aL[mt].w, aH[mt].w, bf.z, bf.w);
                }
        }

        // ========== bias + fast ELU -> Hs[fc&1] (fp16, permuted) ==========
        {
            const float* b1g = b1 + br * DF + fc * 128;
            #pragma unroll
            for (int nt = 0; nt < 2; nt++) {
                int col0 = wn * 16 + nt * 8 + 2 * tig;
                float ba = b1g[col0], bb = b1g[col0 + 1];
                int block = col0 >> 5;
                int p = perm32(col0 & 31);          // even
                int uoff = block * 16 + (p >> 1);
                #pragma unroll
                for (int mt = 0; mt < 2; mt++) {
                    int r0 = wm * 32 + mt * 16 + g;
                    float v00 = elu_fast(c1[mt][nt][0] + ba);
                    float v01 = elu_fast(c1[mt][nt][1] + bb);
                    float v10 = elu_fast(c1[mt][nt][2] + ba);
                    float v11 = elu_fast(c1[mt][nt][3] + bb);
                    __half2 hlo = __floats2half2_rn(v00, v01);
                    __half2 hhi = __floats2half2_rn(v10, v11);
                    Hs[r0 * HS_STRIDE + uoff] = *(uint32_t*)&hlo;
                    Hs[(r0 + 8) * HS_STRIDE + uoff] = *(uint32_t*)&hhi;
                }
            }
        }
        __syncthreads();   // single barrier per fc: Hs[fc&1] writes -> reads.
                           // (writes to Hs[(fc+1)&1] next iter are safe: every warp's
                           //  fc-1 reads of that buffer precede its fc write, which
                           //  precedes this barrier.)

        // ========== GEMM2: acc2[64x256] += H * W2chunk^T, 4 steps of k=32 ==========
        const uint4* w2f = w2base + fc * 4096;
        uint4 bb2[2][4];
        #pragma unroll
        for (int nt = 0; nt < 4; nt++) bb2[0][nt] = __ldg(w2f + c2base + nt * 32);

        #pragma unroll
        for (int step = 0; step < 4; step++) {
            if (step + 1 < 4) {
                int base = (step + 1) * 1024 + c2base;
                #pragma unroll
                for (int nt = 0; nt < 4; nt++)
                    bb2[(step + 1) & 1][nt] = __ldg(w2f + base + nt * 32);
            }
            int cb = step * 16 + 4 * tig;
            uint4 aL[2], aH[2];
            #pragma unroll
            for (int mt = 0; mt < 2; mt++) {
                int r0 = wm * 32 + mt * 16 + g;
                aL[mt] = *(const uint4*)(Hs + r0 * HS_STRIDE + cb);
                aH[mt] = *(const uint4*)(Hs + (r0 + 8) * HS_STRIDE + cb);
            }
            #pragma unroll
            for (int nt = 0; nt < 4; nt++) {
                const uint4 bf = bb2[step & 1][nt];
                #pragma unroll
                for (int mt = 0; mt < 2; mt++) {
                    mma16(acc2[mt][nt], aL[mt].x, aH[mt].x, aL[mt].y, aH[mt].y, bf.x, bf.y);
                    mma16(acc2[mt][nt], aL[mt].z, aH[mt].z, aL[mt].w, aH[mt].w, bf.z, bf.w);
                }
            }
        }
    }

    // ================= epilogue: b2 + exact LayerNorm + scatter =================
    {
        const float* b2g = b2 + br * DH;
        #pragma unroll
        for (int nt = 0; nt < 4; nt++) {
            int col0 = wn * 32 + nt * 8 + 2 * tig;
            float2 bb = *(const float2*)(b2g + col0);
            #pragma unroll
            for (int mt = 0; mt < 2; mt++) {
                acc2[mt][nt][0] += bb.x; acc2[mt][nt][1] += bb.y;
                acc2[mt][nt][2] += bb.x; acc2[mt][nt][3] += bb.y;
            }
        }
        __syncthreads();
        float mu[4], rstd[4];
        #pragma unroll
        for (int rr = 0; rr < 4; rr++) {
            int mt = rr >> 1, hi = rr & 1;
            float sfull = 0.f;
            #pragma unroll
            for (int nt = 0; nt < 4; nt++) sfull += acc2[mt][nt][hi * 2] + acc2[mt][nt][hi * 2 + 1];
            sfull += __shfl_xor_sync(0xffffffffu, sfull, 1);
            sfull += __shfl_xor_sync(0xffffffffu, sfull, 2);
            int row = wm * 32 + mt * 16 + hi * 8 + g;
            if (tig == 0) red[row * 8 + wn] = sfull;
        }
        __syncthreads();
        #pragma unroll
        for (int rr = 0; rr < 4; rr++) {
            int mt = rr >> 1, hi = rr & 1;
            int row = wm * 32 + mt * 16 + hi * 8 + g;
            float s = 0.f;
            #pragma unroll
            for (int w = 0; w < 8; w++) s += red[row * 8 + w];
            mu[rr] = s * (1.f / 256.f);
        }
        __syncthreads();
        #pragma unroll
        for (int rr = 0; rr < 4; rr++) {
            int mt = rr >> 1, hi = rr & 1;
            float sq = 0.f;
            #pragma unroll
            for (int nt = 0; nt < 4; nt++) {
                float d0 = acc2[mt][nt][hi * 2] - mu[rr];
                float d1 = acc2[mt][nt][hi * 2 + 1] - mu[rr];
                sq += d0 * d0 + d1 * d1;
            }
            sq += __shfl_xor_sync(0xffffffffu, sq, 1);
            sq += __shfl_xor_sync(0xffffffffu, sq, 2);
            int row = wm * 32 + mt * 16 + hi * 8 + g;
            if (tig == 0) red[row * 8 + wn] = sq;
        }
        __syncthreads();
        #pragma unroll
        for (int rr = 0; rr < 4; rr++) {
            int mt = rr >> 1, hi = rr & 1;
            int row = wm * 32 + mt * 16 + hi * 8 + g;
            float s = 0.f;
            #pragma unroll
            for (int w = 0; w < 8; w++) s += red[row * 8 + w];
            rstd[rr] = rsqrtf(s * (1.f / 256.f) + 1e-12f);
        }

        const float* gg = gamma + br * DH;
        const float* be = beta + br * DH;
        #pragma unroll
        for (int rr = 0; rr < 4; rr++) {
            int mt = rr >> 1, hi = rr & 1;
            int row = wm * 32 + mt * 16 + hi * 8 + g;
            if (t0 + row < count) {
                float* o = out + (size_t)s_tok[row] * DH;
                #pragma unroll
                for (int nt = 0; nt < 4; nt++) {
                    int col0 = wn * 32 + nt * 8 + 2 * tig;
                    float2 gm = *(const float2*)(gg + col0);
                    float2 bt = *(const float2*)(be + col0);
                    float2 v;
                    v.x = (acc2[mt][nt][hi * 2] - mu[rr]) * rstd[rr] * gm.x + bt.x;
                    v.y = (acc2[mt][nt][hi * 2 + 1] - mu[rr]) * rstd[rr] * gm.y + bt.y;
                    *(float2*)(o + col0) = v;
                }
            }
        }
    }
}

extern "C" void kernel_launch(void* const* d_in, const int* in_sizes, int n_in,
                              void* d_out, int out_size) {
    const float* x     = (const float*)d_in[0];
    const int*   b_seq = (const int*)d_in[1];
    const float* w1    = (const float*)d_in[2];
    const float* b1    = (const float*)d_in[3];
    const float* w2    = (const float*)d_in[4];
    const float* b2    = (const float*)d_in[5];
    const float* gamma = (const float*)d_in[6];
    const float* beta  = (const float*)d_in[7];
    float* out = (float*)d_out;

    const int smem_bytes = SMEM_U32 * 4;
    cudaFuncSetAttribute(ffn_mma_kernel, cudaFuncAttributeMaxDynamicSharedMemorySize, smem_bytes);

    reset_counts_kernel<<<1, 32>>>();
    bucket_kernel<<<NTOK / 256, 256>>>(b_seq);
    prep_w1_kernel<<<NB * DF * DH / 4 / 256, 256>>>(w1);
    prep_w2_kernel<<<NB * DH * DF / 4 / 256, 256>>>(w2);
    zero_kernel<<<(NTOK * 64) / 256, 256>>>(b_seq, (float4*)out);
    ffn_mma_kernel<<<dim3(NTOK / TM, NB), THREADS, smem_bytes>>>(x, b1, b2, gamma, beta, out);
}

// round 14
// speedup vs baseline: 7.4509x; 1.0655x over previous
#include <cuda_runtime.h>
#include <cuda_fp16.h>
#include <math.h>
#include <stdint.h>

#define NTOK 65536
#define DH 256
#define DF 1024
#define NB 4
#define TM 64
#define THREADS 512

#define XS_STRIDE 144   // u32 units; ≡16 (mod 32): conflict-free uint4 LDS phases
#define HS_STRIDE 80
#define HS_BUF (64 * HS_STRIDE)

// smem offsets in u32 units
#define OFF_TOK 0
#define OFF_RED 64                 // 64 rows x 8 warp-partials
#define OFF_XS 576
#define OFF_HS (OFF_XS + 64 * XS_STRIDE)
#define SMEM_U32 (OFF_HS + 2 * HS_BUF)

__device__ int g_counts[NB];
__device__ int g_idx[NB * NTOK];
// fp16 weights in m16n8k16 fragment-permuted layout.
// Each (fc, step, f/h) cell holds 32 fp16 = 4 uint4.
__device__ uint4 g_w1h[NB * 8 * 8 * 128 * 4];   // [br][fc8][step8][f128][4 uint4]
__device__ uint4 g_w2h[NB * 8 * 4 * 256 * 4];   // [br][fc8][step4][h256][4 uint4]

static __device__ __forceinline__ void mma16(float* c,
    uint32_t a0, uint32_t a1, uint32_t a2, uint32_t a3, uint32_t b0, uint32_t b1) {
    asm volatile("mma.sync.aligned.m16n8k16.row.col.f32.f16.f16.f32 "
                 "{%0,%1,%2,%3}, {%4,%5,%6,%7}, {%8,%9}, {%0,%1,%2,%3};"
                 : "+f"(c[0]), "+f"(c[1]), "+f"(c[2]), "+f"(c[3])
                 : "r"(a0), "r"(a1), "r"(a2), "r"(a3), "r"(b0), "r"(b1));
}

// fast ELU: abs error ~5e-7 near 0 (<< fp16 rounding of H)
static __device__ __forceinline__ float elu_fast(float v) {
    return v > 0.f ? v : (__expf(v) - 1.f);
}

// permutation within a 32-k block: element position for k
// t=(k&7)>>1, grp=(k>>4)&1, hi=(k>>3)&1, odd=k&1 -> p = t*8 + grp*4 + hi*2 + odd
static __device__ __forceinline__ int perm32(int kk) {
    return ((kk & 7) >> 1) * 8 + ((kk >> 4) & 1) * 4 + ((kk >> 3) & 1) * 2 + (kk & 1);
}

__global__ void reset_counts_kernel() {
    if (threadIdx.x < NB) g_counts[threadIdx.x] = 0;
}
__global__ void bucket_kernel(const int* __restrict__ b_seq) {
    int i = blockIdx.x * blockDim.x + threadIdx.x;
    int b = b_seq[i];
    if (b > 0) {
        int pos = atomicAdd(&g_counts[b - 1], 1);
        g_idx[(b - 1) * NTOK + pos] = i;
    }
}
__global__ void zero_kernel(const int* __restrict__ b_seq, float4* __restrict__ out) {
    int gid = blockIdx.x * blockDim.x + threadIdx.x;
    int tok = gid >> 6;
    if (b_seq[tok] == 0) out[gid] = make_float4(0.f, 0.f, 0.f, 0.f);
}

// w1 [NB][DF][DH] float -> fp16 fragment-permuted
__global__ void prep_w1_kernel(const float* __restrict__ w1) {
    int t = blockIdx.x * blockDim.x + threadIdx.x;
    int e = t * 4;
    int br = e >> 18;
    int rem = e & 262143;
    int f = rem >> 8;
    int k = rem & 255;
    float4 v = *(const float4*)(w1 + e);
    int fc = f >> 7, fl = f & 127, step = k >> 5, kk = k & 31;   // kk % 4 == 0
    int p = perm32(kk);                                           // even
    __half2* dst = (__half2*)g_w1h + (((((br * 8 + fc) * 8 + step) * 128 + fl) * 32) + p) / 2;
    dst[0] = __floats2half2_rn(v.x, v.y);
    dst[4] = __floats2half2_rn(v.z, v.w);   // k+2,k+3 -> p+8
}
// w2 [NB][DH][DF] float -> fp16 fragment-permuted
__global__ void prep_w2_kernel(const float* __restrict__ w2) {
    int t = blockIdx.x * blockDim.x + threadIdx.x;
    int e = t * 4;
    int br = e >> 18;
    int rem = e & 262143;
    int h = rem >> 10;
    int f = rem & 1023;
    float4 v = *(const float4*)(w2 + e);
    int fc = f >> 7, fl = f & 127, step = fl >> 5, kk = fl & 31;  // kk % 4 == 0
    int p = perm32(kk);
    __half2* dst = (__half2*)g_w2h + (((((br * 8 + fc) * 4 + step) * 256 + h) * 32) + p) / 2;
    dst[0] = __floats2half2_rn(v.x, v.y);
    dst[4] = __floats2half2_rn(v.z, v.w);
}

__global__ __launch_bounds__(THREADS, 1)
void ffn_mma_kernel(const float* __restrict__ x,
                    const float* __restrict__ b1, const float* __restrict__ b2,
                    const float* __restrict__ gamma, const float* __restrict__ beta,
                    float* __restrict__ out)
{
    const int br = blockIdx.y;
    const int count = g_counts[br];
    const int t0 = blockIdx.x * TM;
    if (t0 >= count) return;

    extern __shared__ uint32_t smem[];
    int* s_tok = (int*)(smem + OFF_TOK);
    float* red = (float*)(smem + OFF_RED);
    uint32_t* Xs = smem + OFF_XS;

    const int tid = threadIdx.x;
    const int wid = tid >> 5, lane = tid & 31;
    const int g = lane >> 2, tig = lane & 3;
    const int wm = wid & 1, wn = wid >> 1;   // 2 m-warps x 8 n-warps

    if (tid < TM) {
        int r = t0 + tid;
        s_tok[tid] = g_idx[br * NTOK + (r < count ? r : count - 1)];
    }
    __syncthreads();

    // ---- stage X tile (once), fp16 + k-permuted: 8 threads/row, one 32-k block each ----
    {
        int row = tid >> 3, q = tid & 7;
        const float4* src = (const float4*)(x + (size_t)s_tok[row] * DH) + q * 8;
        uint32_t* xr = Xs + row * XS_STRIDE + q * 16;
        #pragma unroll
        for (int j = 0; j < 8; j++) {
            float4 d = src[j];
            int p = perm32(j * 4);
            __half2 h01 = __floats2half2_rn(d.x, d.y);
            __half2 h23 = __floats2half2_rn(d.z, d.w);
            uint32_t* dst = xr + (p >> 1);
            dst[0] = *(uint32_t*)&h01;
            dst[4] = *(uint32_t*)&h23;
        }
    }

    // lane-constant uint4 stream bases into the permuted weight arrays.
    // B-fragment streams are LINEAR across fc:
    //   GEMM1: w1s + t1*512,  t1 = fc*8 + s,  t1 in [0,64)
    //   GEMM2: w2s + t2*1024, t2 = fc*4 + s,  t2 in [0,32)
    const int c1base = ((wn * 16 + g) << 2) + tig;
    const int c2base = ((wn * 32 + g) << 2) + tig;
    const uint4* w1s = g_w1h + (size_t)br * 8 * 4096 + c1base;
    const uint4* w2s = g_w2h + (size_t)br * 8 * 4096 + c2base;

    float acc2[2][4][4];
    #pragma unroll
    for (int a = 0; a < 2; a++)
        #pragma unroll
        for (int bq = 0; bq < 4; bq++)
            #pragma unroll
            for (int cq = 0; cq < 4; cq++) acc2[a][bq][cq] = 0.f;

    // seed GEMM1 ring (t1 = 0)
    uint4 bb1[2][2];
    #pragma unroll
    for (int nt = 0; nt < 2; nt++) bb1[0][nt] = __ldg(w1s + nt * 32);
    uint4 bb2[2][4];

    __syncthreads();

    #pragma unroll 1
    for (int fc = 0; fc < 8; fc++) {
        uint32_t* Hs = smem + OFF_HS + (fc & 1) * HS_BUF;

        // ========== GEMM1: C1[64x128] = X * W1chunk^T, 8 steps of k=32 ==========
        float c1[2][2][4];
        #pragma unroll
        for (int a = 0; a < 2; a++)
            #pragma unroll
            for (int bq = 0; bq < 2; bq++)
                #pragma unroll
                for (int cq = 0; cq < 4; cq++) c1[a][bq][cq] = 0.f;

        #pragma unroll
        for (int s = 0; s < 8; s++) {
            int t1 = fc * 8 + s;
            if (t1 + 1 < 64) {      // continuous cross-fc prefetch, slot (s+1)&1
                const uint4* p = w1s + (t1 + 1) * 512;
                #pragma unroll
                for (int nt = 0; nt < 2; nt++)
                    bb1[(s + 1) & 1][nt] = __ldg(p + nt * 32);
            }
            int cb = s * 16 + 4 * tig;
            uint4 aL[2], aH[2];
            #pragma unroll
            for (int mt = 0; mt < 2; mt++) {
                int r0 = wm * 32 + mt * 16 + g;
                aL[mt] = *(const uint4*)(Xs + r0 * XS_STRIDE + cb);
                aH[mt] = *(const uint4*)(Xs + (r0 + 8) * XS_STRIDE + cb);
            }
            #pragma unroll
            for (int mt = 0; mt < 2; mt++)
                #pragma unroll
                for (int nt = 0; nt < 2; nt++) {
                    const uint4 bf = bb1[s & 1][nt];
                    mma16(c1[mt][nt], aL[mt].x, aH[mt].x, aL[mt].y, aH[mt].y, bf.x, bf.y);
                    mma16(c1[mt][nt], aL[mt].z, aH[mt].z, aL[mt].w, aH[mt].w, bf.z, bf.w);
                }
        }

        // ========== bias + fast ELU -> Hs[fc&1] (fp16, permuted) ==========
        {
            const float* b1g = b1 + br * DF + fc * 128;
            #pragma unroll
            for (int nt = 0; nt < 2; nt++) {
                int col0 = wn * 16 + nt * 8 + 2 * tig;
                float ba = b1g[col0], bb = b1g[col0 + 1];
                int block = col0 >> 5;
                int p = perm32(col0 & 31);          // even
                int uoff = block * 16 + (p >> 1);
                #pragma unroll
                for (int mt = 0; mt < 2; mt++) {
                    int r0 = wm * 32 + mt * 16 + g;
                    float v00 = elu_fast(c1[mt][nt][0] + ba);
                    float v01 = elu_fast(c1[mt][nt][1] + bb);
                    float v10 = elu_fast(c1[mt][nt][2] + ba);
                    float v11 = elu_fast(c1[mt][nt][3] + bb);
                    __half2 hlo = __floats2half2_rn(v00, v01);
                    __half2 hhi = __floats2half2_rn(v10, v11);
                    Hs[r0 * HS_STRIDE + uoff] = *(uint32_t*)&hlo;
                    Hs[(r0 + 8) * HS_STRIDE + uoff] = *(uint32_t*)&hhi;
                }
            }
        }
        if (fc == 0) {    // seed GEMM2 ring before the barrier so the barrier hides L2
            #pragma unroll
            for (int nt = 0; nt < 4; nt++) bb2[0][nt] = __ldg(w2s + nt * 32);
        }
        __syncthreads();   // single barrier per fc: Hs[fc&1] writes -> reads.

        // ========== GEMM2: acc2[64x256] += H * W2chunk^T, 4 steps of k=32 ==========
        #pragma unroll
        for (int s = 0; s < 4; s++) {
            int t2 = fc * 4 + s;
            if (t2 + 1 < 32) {   // cross-fc prefetch: next fc's step0 lands during GEMM1+barrier
                const uint4* p = w2s + (t2 + 1) * 1024;
                #pragma unroll
                for (int nt = 0; nt < 4; nt++)
                    bb2[(s + 1) & 1][nt] = __ldg(p + nt * 32);
            }
            int cb = s * 16 + 4 * tig;
            uint4 aL[2], aH[2];
            #pragma unroll
            for (int mt = 0; mt < 2; mt++) {
                int r0 = wm * 32 + mt * 16 + g;
                aL[mt] = *(const uint4*)(Hs + r0 * HS_STRIDE + cb);
                aH[mt] = *(const uint4*)(Hs + (r0 + 8) * HS_STRIDE + cb);
            }
            #pragma unroll
            for (int nt = 0; nt < 4; nt++) {
                const uint4 bf = bb2[s & 1][nt];
                #pragma unroll
                for (int mt = 0; mt < 2; mt++) {
                    mma16(acc2[mt][nt], aL[mt].x, aH[mt].x, aL[mt].y, aH[mt].y, bf.x, bf.y);
                    mma16(acc2[mt][nt], aL[mt].z, aH[mt].z, aL[mt].w, aH[mt].w, bf.z, bf.w);
                }
            }
        }
    }

    // ================= epilogue: b2 + exact LayerNorm + scatter =================
    {
        const float* b2g = b2 + br * DH;
        #pragma unroll
        for (int nt = 0; nt < 4; nt++) {
            int col0 = wn * 32 + nt * 8 + 2 * tig;
            float2 bb = *(const float2*)(b2g + col0);
            #pragma unroll
            for (int mt = 0; mt < 2; mt++) {
                acc2[mt][nt][0] += bb.x; acc2[mt][nt][1] += bb.y;
                acc2[mt][nt][2] += bb.x; acc2[mt][nt][3] += bb.y;
            }
        }
        __syncthreads();
        float mu[4], rstd[4];
        #pragma unroll
        for (int rr = 0; rr < 4; rr++) {
            int mt = rr >> 1, hi = rr & 1;
            float sfull = 0.f;
            #pragma unroll
            for (int nt = 0; nt < 4; nt++) sfull += acc2[mt][nt][hi * 2] + acc2[mt][nt][hi * 2 + 1];
            sfull += __shfl_xor_sync(0xffffffffu, sfull, 1);
            sfull += __shfl_xor_sync(0xffffffffu, sfull, 2);
            int row = wm * 32 + mt * 16 + hi * 8 + g;
            if (tig == 0) red[row * 8 + wn] = sfull;
        }
        __syncthreads();
        #pragma unroll
        for (int rr = 0; rr < 4; rr++) {
            int mt = rr >> 1, hi = rr & 1;
            int row = wm * 32 + mt * 16 + hi * 8 + g;
            float s = 0.f;
            #pragma unroll
            for (int w = 0; w < 8; w++) s += red[row * 8 + w];
            mu[rr] = s * (1.f / 256.f);
        }
        __syncthreads();
        #pragma unroll
        for (int rr = 0; rr < 4; rr++) {
            int mt = rr >> 1, hi = rr & 1;
            float sq = 0.f;
            #pragma unroll
            for (int nt = 0; nt < 4; nt++) {
                float d0 = acc2[mt][nt][hi * 2] - mu[rr];
                float d1 = acc2[mt][nt][hi * 2 + 1] - mu[rr];
                sq += d0 * d0 + d1 * d1;
            }
            sq += __shfl_xor_sync(0xffffffffu, sq, 1);
            sq += __shfl_xor_sync(0xffffffffu, sq, 2);
            int row = wm * 32 + mt * 16 + hi * 8 + g;
            if (tig == 0) red[row * 8 + wn] = sq;
        }
        __syncthreads();
        #pragma unroll
        for (int rr = 0; rr < 4; rr++) {
            int mt = rr >> 1, hi = rr & 1;
            int row = wm * 32 + mt * 16 + hi * 8 + g;
            float s = 0.f;
            #pragma unroll
            for (int w = 0; w < 8; w++) s += red[row * 8 + w];
            rstd[rr] = rsqrtf(s * (1.f / 256.f) + 1e-12f);
        }

        const float* gg = gamma + br * DH;
        const float* be = beta + br * DH;
        #pragma unroll
        for (int rr = 0; rr < 4; rr++) {
            int mt = rr >> 1, hi = rr & 1;
            int row = wm * 32 + mt * 16 + hi * 8 + g;
            if (t0 + row < count) {
                float* o = out + (size_t)s_tok[row] * DH;
                #pragma unroll
                for (int nt = 0; nt < 4; nt++) {
                    int col0 = wn * 32 + nt * 8 + 2 * tig;
                    float2 gm = *(const float2*)(gg + col0);
                    float2 bt = *(const float2*)(be + col0);
                    float2 v;
                    v.x = (acc2[mt][nt][hi * 2] - mu[rr]) * rstd[rr] * gm.x + bt.x;
                    v.y = (acc2[mt][nt][hi * 2 + 1] - mu[rr]) * rstd[rr] * gm.y + bt.y;
                    *(float2*)(o + col0) = v;
                }
            }
        }
    }
}

extern "C" void kernel_launch(void* const* d_in, const int* in_sizes, int n_in,
                              void* d_out, int out_size) {
    const float* x     = (const float*)d_in[0];
    const int*   b_seq = (const int*)d_in[1];
    const float* w1    = (const float*)d_in[2];
    const float* b1    = (const float*)d_in[3];
    const float* w2    = (const float*)d_in[4];
    const float* b2    = (const float*)d_in[5];
    const float* gamma = (const float*)d_in[6];
    const float* beta  = (const float*)d_in[7];
    float* out = (float*)d_out;

    const int smem_bytes = SMEM_U32 * 4;
    cudaFuncSetAttribute(ffn_mma_kernel, cudaFuncAttributeMaxDynamicSharedMemorySize, smem_bytes);

    reset_counts_kernel<<<1, 32>>>();
    bucket_kernel<<<NTOK / 256, 256>>>(b_seq);
    prep_w1_kernel<<<NB * DF * DH / 4 / 256, 256>>>(w1);
    prep_w2_kernel<<<NB * DH * DF / 4 / 256, 256>>>(w2);
    zero_kernel<<<(NTOK * 64) / 256, 256>>>(b_seq, (float4*)out);
    ffn_mma_kernel<<<dim3(NTOK / TM, NB), THREADS, smem_bytes>>>(x, b1, b2, gamma, beta, out);
}